// round 1
// baseline (speedup 1.0000x reference)
#include <cuda_runtime.h>
#include <cstdint>

#define BB   128      // batch
#define TT   512      // time
#define DIN  512      // input dim (also 2H for layer 1)
#define HH   256      // hidden
#define G4   1024     // 4*H
#define NBLK 128      // recurrent grid size

#define HN_OFF 33554432ULL              // B*T*512
#define CN_OFF (HN_OFF + 131072ULL)     // + 4*B*H

// ---------------- device scratch (static, no runtime alloc) ----------------
__device__ __align__(256) float g_xT[(size_t)TT * BB * DIN];          // 128 MB
__device__ __align__(256) float g_xproj[2ULL * TT * BB * G4];         // 512 MB
__device__ __align__(256) float g_inp2[(size_t)TT * BB * DIN];        // 128 MB
__device__ __align__(256) float g_hbuf[2][2][BB][HH];                 // parity, dir
__device__ unsigned long long g_bar = 0ULL;

// ---------------- grid barrier (monotonic counter, persistent-safe) --------
__device__ __forceinline__ void gridbar()
{
    __syncthreads();
    if (threadIdx.x == 0) {
        __threadfence();
        unsigned long long t = atomicAdd(&g_bar, 1ULL) + 1ULL;
        unsigned long long target = ((t + NBLK - 1ULL) / NBLK) * NBLK;
        while (atomicAdd(&g_bar, 0ULL) < target) { __nanosleep(64); }
        __threadfence();
    }
    __syncthreads();
}

// ---------------- transpose x (B,T,D) -> (T,B,D) ---------------------------
__global__ void k_transpose(const float* __restrict__ x)
{
    int i = blockIdx.x * blockDim.x + threadIdx.x;      // float4 index
    const int N4 = TT * BB * (DIN / 4);
    if (i >= N4) return;
    int k4 = i & (DIN / 4 - 1);
    int rest = i / (DIN / 4);
    int b = rest & (BB - 1);
    int t = rest / BB;
    float4 v = ((const float4*)x)[((size_t)b * TT + t) * (DIN / 4) + k4];
    ((float4*)g_xT)[((size_t)t * BB + b) * (DIN / 4) + k4] = v;
}

// ---------------- input-projection GEMM ------------------------------------
// C[d][m][n'] = sum_k A[m][k] * W[d][row(n')][k] + bias, n' = u*4+g (unit-major)
__global__ void __launch_bounds__(256) k_gemm_xproj(
    const float* __restrict__ Wih, const float* __restrict__ bih,
    const float* __restrict__ bhh, int layer)
{
    const int dir = blockIdx.z;
    const float* A = (layer == 0) ? g_xT : g_inp2;
    const float* Wd = Wih + (size_t)(layer * 2 + dir) * G4 * DIN;
    const float* bi = bih + (layer * 2 + dir) * G4;
    const float* bh = bhh + (layer * 2 + dir) * G4;
    float* C = g_xproj + (size_t)dir * TT * BB * G4;

    __shared__ __align__(16) float As[8][128];
    __shared__ __align__(16) float Bs[8][128];

    const int tid = threadIdx.x;
    const int tx = tid & 15, ty = tid >> 4;
    const int mb = blockIdx.y * 128, nb = blockIdx.x * 128;

    const int lm = tid >> 1;            // 0..127
    const int lk = (tid & 1) * 4;       // 0 or 4

    const int nglob = nb + lm;
    const int brow = (nglob & 3) * HH + (nglob >> 2);   // W_ih row for permuted col

    float acc[8][8];
#pragma unroll
    for (int i = 0; i < 8; i++)
#pragma unroll
        for (int j = 0; j < 8; j++) acc[i][j] = 0.f;

    float biasr[8];
#pragma unroll
    for (int j = 0; j < 8; j++) {
        int n = nb + tx * 8 + j;
        int r = (n & 3) * HH + (n >> 2);
        biasr[j] = bi[r] + bh[r];
    }

    const float* Aptr = A + (size_t)(mb + lm) * DIN + lk;
    const float* Bptr = Wd + (size_t)brow * DIN + lk;

    for (int kt = 0; kt < DIN; kt += 8) {
        float4 av = *(const float4*)(Aptr + kt);
        float4 bv = *(const float4*)(Bptr + kt);
        __syncthreads();
        As[lk + 0][lm] = av.x; As[lk + 1][lm] = av.y;
        As[lk + 2][lm] = av.z; As[lk + 3][lm] = av.w;
        Bs[lk + 0][lm] = bv.x; Bs[lk + 1][lm] = bv.y;
        Bs[lk + 2][lm] = bv.z; Bs[lk + 3][lm] = bv.w;
        __syncthreads();
#pragma unroll
        for (int k = 0; k < 8; k++) {
            float4 a0 = *(const float4*)&As[k][ty * 8];
            float4 a1 = *(const float4*)&As[k][ty * 8 + 4];
            float4 b0 = *(const float4*)&Bs[k][tx * 8];
            float4 b1 = *(const float4*)&Bs[k][tx * 8 + 4];
            float a[8] = {a0.x, a0.y, a0.z, a0.w, a1.x, a1.y, a1.z, a1.w};
            float b[8] = {b0.x, b0.y, b0.z, b0.w, b1.x, b1.y, b1.z, b1.w};
#pragma unroll
            for (int i = 0; i < 8; i++)
#pragma unroll
                for (int j = 0; j < 8; j++) acc[i][j] += a[i] * b[j];
        }
    }

#pragma unroll
    for (int i = 0; i < 8; i++) {
        float* crow = C + (size_t)(mb + ty * 8 + i) * G4 + (nb + tx * 8);
        float4 v0 = make_float4(acc[i][0] + biasr[0], acc[i][1] + biasr[1],
                                acc[i][2] + biasr[2], acc[i][3] + biasr[3]);
        float4 v1 = make_float4(acc[i][4] + biasr[4], acc[i][5] + biasr[5],
                                acc[i][6] + biasr[6], acc[i][7] + biasr[7]);
        *(float4*)crow = v0;
        *(float4*)(crow + 4) = v1;
    }
}

// ---------------- recurrent persistent kernel ------------------------------
__device__ __forceinline__ float sigm(float x) { return 1.f / (1.f + expf(-x)); }

#define SMEM_REC (64 * 256 * 4 + 36 * 256 * 4)   // Bs + padded h tile = 100 KB

__global__ void __launch_bounds__(128) k_lstm(
    const float* __restrict__ Whh, const int* __restrict__ lengths,
    float* __restrict__ dout, int layer)
{
    extern __shared__ float sm[];
    float* Bs = sm;                 // [256][64]  weights, n' = ulocal*4+g
    float* Ah = sm + 64 * 256;      // [256][36]  h tile (padded)

    const int bx  = blockIdx.x;
    const int dir = bx >> 6;
    const int cta = bx & 63;
    const int bb  = (cta >> 4) * 32;    // batch base (4 slices of 32)
    const int hb  = (cta & 15) * 16;    // hidden base (16 slices of 16)
    const int tid = threadIdx.x;
    const int tx  = tid & 15, ty = tid >> 4;   // ty 0..7

    const float* W = Whh + (size_t)(layer * 2 + dir) * G4 * HH;

    // resident weight load (once per launch)
    for (int idx = tid; idx < 64 * 256; idx += 128) {
        int nl = idx >> 8; int k = idx & 255;
        int row = (nl & 3) * HH + hb + (nl >> 2);
        Bs[k * 64 + nl] = W[(size_t)row * HH + k];
    }

    const int u = hb + tx;
    int lenr[4];
#pragma unroll
    for (int i = 0; i < 4; i++) {
        int b = bb + ty * 4 + i;
        lenr[i] = lengths[b];
        g_hbuf[0][dir][b][u] = 0.f;     // zero parity-0 h
    }
    float cs[4] = {0.f, 0.f, 0.f, 0.f};
    float hs[4] = {0.f, 0.f, 0.f, 0.f};

    gridbar();

    const int bl = tid >> 2;            // 0..31 (batch row for staging)
    const int kc = (tid & 3) * 64;      // k chunk for staging

    for (int s = 0; s < TT; s++) {
        int t = dir ? (TT - 1 - s) : s;
        int p = s & 1;

        // stage h tile: global (L2) -> smem transposed [k][m]
        const float* hsrc = &g_hbuf[p][dir][bb + bl][kc];
#pragma unroll
        for (int i = 0; i < 16; i++) {
            float4 v = __ldcg((const float4*)(hsrc + i * 4));
            int k0 = kc + i * 4;
            Ah[(k0 + 0) * 36 + bl] = v.x;
            Ah[(k0 + 1) * 36 + bl] = v.y;
            Ah[(k0 + 2) * 36 + bl] = v.z;
            Ah[(k0 + 3) * 36 + bl] = v.w;
        }
        __syncthreads();

        float acc[4][4];
#pragma unroll
        for (int i = 0; i < 4; i++)
#pragma unroll
            for (int j = 0; j < 4; j++) acc[i][j] = 0.f;

#pragma unroll 8
        for (int k = 0; k < HH; k++) {
            float4 a  = *(const float4*)&Ah[k * 36 + (ty << 2)];
            float4 b4 = *(const float4*)&Bs[(k << 6) + (tx << 2)];
            acc[0][0] += a.x * b4.x; acc[0][1] += a.x * b4.y;
            acc[0][2] += a.x * b4.z; acc[0][3] += a.x * b4.w;
            acc[1][0] += a.y * b4.x; acc[1][1] += a.y * b4.y;
            acc[1][2] += a.y * b4.z; acc[1][3] += a.y * b4.w;
            acc[2][0] += a.z * b4.x; acc[2][1] += a.z * b4.y;
            acc[2][2] += a.z * b4.z; acc[2][3] += a.z * b4.w;
            acc[3][0] += a.w * b4.x; acc[3][1] += a.w * b4.y;
            acc[3][2] += a.w * b4.z; acc[3][3] += a.w * b4.w;
        }

        const float* xp = g_xproj + (size_t)dir * TT * BB * G4
                        + ((size_t)t * BB + bb + ty * 4) * G4 + (size_t)u * 4;
#pragma unroll
        for (int i = 0; i < 4; i++) {
            float4 g = *(const float4*)(xp + (size_t)i * G4);
            float gi = sigm(acc[i][0] + g.x);
            float gf = sigm(acc[i][1] + g.y);
            float gg = tanhf(acc[i][2] + g.z);
            float go = sigm(acc[i][3] + g.w);
            float cn = gf * cs[i] + gi * gg;
            float hn = go * tanhf(cn);
            bool val = (t < lenr[i]);
            if (val) { cs[i] = cn; hs[i] = hn; }
            float ov = val ? hn : 0.f;
            int b = bb + ty * 4 + i;
            if (layer == 0)
                g_inp2[((size_t)t * BB + b) * 512 + dir * HH + u] = ov;
            else
                dout[((size_t)b * TT + t) * 512 + dir * HH + u] = ov;
            __stcg(&g_hbuf[1 - p][dir][b][u], hs[i]);
        }
        gridbar();
    }

    // final h_n / c_n
#pragma unroll
    for (int i = 0; i < 4; i++) {
        int b = bb + ty * 4 + i;
        size_t o = (size_t)((layer * 2 + dir) * BB + b) * HH + u;
        dout[HN_OFF + o] = hs[i];
        dout[CN_OFF + o] = cs[i];
    }
}

// ---------------- launch -----------------------------------------------------
extern "C" void kernel_launch(void* const* d_in, const int* in_sizes, int n_in,
                              void* d_out, int out_size)
{
    const float* x   = (const float*)d_in[0];
    const int*   len = (const int*)d_in[1];
    const float* Wih = (const float*)d_in[2];
    const float* Whh = (const float*)d_in[3];
    const float* bih = (const float*)d_in[4];
    const float* bhh = (const float*)d_in[5];
    float* out = (float*)d_out;

    cudaFuncSetAttribute(k_lstm, cudaFuncAttributeMaxDynamicSharedMemorySize, SMEM_REC);

    // transpose x -> (T,B,D)
    {
        int n4 = TT * BB * (DIN / 4);
        k_transpose<<<(n4 + 1023) / 1024, 1024>>>(x);
    }
    // layer 0
    k_gemm_xproj<<<dim3(8, 512, 2), 256>>>(Wih, bih, bhh, 0);
    k_lstm<<<NBLK, 128, SMEM_REC>>>(Whh, len, out, 0);
    // layer 1
    k_gemm_xproj<<<dim3(8, 512, 2), 256>>>(Wih, bih, bhh, 1);
    k_lstm<<<NBLK, 128, SMEM_REC>>>(Whh, len, out, 1);
}

// round 2
// speedup vs baseline: 1.1253x; 1.1253x over previous
#include <cuda_runtime.h>
#include <cstdint>

#define BB   128      // batch
#define TT   512      // time
#define DIN  512      // input dim (also 2H for layer 1)
#define HH   256      // hidden
#define G4   1024     // 4*H
#define NBLK 128      // recurrent grid size

#define HN_OFF 33554432ULL              // B*T*512
#define CN_OFF (HN_OFF + 131072ULL)     // + 4*B*H

// ---------------- device scratch (static, no runtime alloc) ----------------
__device__ __align__(256) float g_xT[(size_t)TT * BB * DIN];
__device__ __align__(256) float g_xproj[2ULL * TT * BB * G4];
__device__ __align__(256) float g_inp2[(size_t)TT * BB * DIN];
__device__ __align__(256) float g_hbuf[2][2][BB][HH];                 // parity, dir
__device__ unsigned g_flag[2][4][16];                                 // dir, bgroup, hslice
__device__ unsigned long long g_bar = 0ULL;

// ---------------- f32x2 packed math helpers --------------------------------
__device__ __forceinline__ unsigned long long pack2(float x) {
    unsigned long long r;
    asm("mov.b64 %0, {%1, %1};" : "=l"(r) : "f"(x));
    return r;
}
__device__ __forceinline__ void fma2(unsigned long long& d,
                                     unsigned long long a, unsigned long long b) {
    asm("fma.rn.f32x2 %0, %1, %2, %0;" : "+l"(d) : "l"(a), "l"(b));
}
__device__ __forceinline__ float2 unpack2(unsigned long long v) {
    float2 f;
    asm("mov.b64 {%0, %1}, %2;" : "=f"(f.x), "=f"(f.y) : "l"(v));
    return f;
}
__device__ __forceinline__ float tanhfast(float x) {
    float y; asm("tanh.approx.f32 %0, %1;" : "=f"(y) : "f"(x)); return y;
}
__device__ __forceinline__ float sigmfast(float x) {
    return fmaf(0.5f, tanhfast(0.5f * x), 0.5f);
}

// ---------------- acquire/release flag ops ----------------------------------
__device__ __forceinline__ unsigned ld_acq(const unsigned* p) {
    unsigned v; asm volatile("ld.acquire.gpu.u32 %0, [%1];" : "=r"(v) : "l"(p)); return v;
}
__device__ __forceinline__ void st_rel(unsigned* p, unsigned v) {
    asm volatile("st.release.gpu.u32 [%0], %1;" :: "l"(p), "r"(v));
}

// ---------------- global barrier (monotonic, used once per launch) ----------
__device__ __forceinline__ void gridbar()
{
    __syncthreads();
    if (threadIdx.x == 0) {
        __threadfence();
        unsigned long long t = atomicAdd(&g_bar, 1ULL) + 1ULL;
        unsigned long long target = ((t + NBLK - 1ULL) / NBLK) * NBLK;
        while (atomicAdd(&g_bar, 0ULL) < target) { __nanosleep(64); }
        __threadfence();
    }
    __syncthreads();
}

// ---------------- transpose x (B,T,D) -> (T,B,D) ---------------------------
__global__ void k_transpose(const float* __restrict__ x)
{
    int i = blockIdx.x * blockDim.x + threadIdx.x;
    const int N4 = TT * BB * (DIN / 4);
    if (i >= N4) return;
    int k4 = i & (DIN / 4 - 1);
    int rest = i / (DIN / 4);
    int b = rest & (BB - 1);
    int t = rest / BB;
    float4 v = ((const float4*)x)[((size_t)b * TT + t) * (DIN / 4) + k4];
    ((float4*)g_xT)[((size_t)t * BB + b) * (DIN / 4) + k4] = v;
}

// ---------------- input-projection GEMM (FFMA2) ------------------------------
// C[d][m][n'] = sum_k A[m][k] * W[d][row(n')][k] + bias, n' = u*4+g (unit-major)
__global__ void __launch_bounds__(256) k_gemm_xproj(
    const float* __restrict__ Wih, const float* __restrict__ bih,
    const float* __restrict__ bhh, int layer)
{
    const int dir = blockIdx.z;
    const float* A = (layer == 0) ? g_xT : g_inp2;
    const float* Wd = Wih + (size_t)(layer * 2 + dir) * G4 * DIN;
    const float* bi = bih + (layer * 2 + dir) * G4;
    const float* bh = bhh + (layer * 2 + dir) * G4;
    float* C = g_xproj + (size_t)dir * TT * BB * G4;

    __shared__ __align__(16) float As[8][128];
    __shared__ __align__(16) float Bs[8][128];

    const int tid = threadIdx.x;
    const int tx = tid & 15, ty = tid >> 4;
    const int mb = blockIdx.y * 128, nb = blockIdx.x * 128;

    const int lm = tid >> 1;            // 0..127
    const int lk = (tid & 1) * 4;       // 0 or 4

    const int nglob = nb + lm;
    const int brow = (nglob & 3) * HH + (nglob >> 2);   // W_ih row for permuted col

    unsigned long long acc2[8][4];
#pragma unroll
    for (int i = 0; i < 8; i++)
#pragma unroll
        for (int j = 0; j < 4; j++) acc2[i][j] = 0ULL;

    float biasr[8];
#pragma unroll
    for (int j = 0; j < 8; j++) {
        int n = nb + tx * 8 + j;
        int r = (n & 3) * HH + (n >> 2);
        biasr[j] = bi[r] + bh[r];
    }

    const float* Aptr = A + (size_t)(mb + lm) * DIN + lk;
    const float* Bptr = Wd + (size_t)brow * DIN + lk;

    float4 av = *(const float4*)(Aptr);
    float4 bv = *(const float4*)(Bptr);

    for (int kt = 0; kt < DIN; kt += 8) {
        __syncthreads();
        As[lk + 0][lm] = av.x; As[lk + 1][lm] = av.y;
        As[lk + 2][lm] = av.z; As[lk + 3][lm] = av.w;
        Bs[lk + 0][lm] = bv.x; Bs[lk + 1][lm] = bv.y;
        Bs[lk + 2][lm] = bv.z; Bs[lk + 3][lm] = bv.w;
        __syncthreads();
        if (kt + 8 < DIN) {
            av = *(const float4*)(Aptr + kt + 8);
            bv = *(const float4*)(Bptr + kt + 8);
        }
#pragma unroll
        for (int k = 0; k < 8; k++) {
            float4 a0 = *(const float4*)&As[k][ty * 8];
            float4 a1 = *(const float4*)&As[k][ty * 8 + 4];
            ulonglong2 bA = *(const ulonglong2*)&Bs[k][tx * 8];
            ulonglong2 bB = *(const ulonglong2*)&Bs[k][tx * 8 + 4];
            unsigned long long p;
            p = pack2(a0.x);
            fma2(acc2[0][0], p, bA.x); fma2(acc2[0][1], p, bA.y);
            fma2(acc2[0][2], p, bB.x); fma2(acc2[0][3], p, bB.y);
            p = pack2(a0.y);
            fma2(acc2[1][0], p, bA.x); fma2(acc2[1][1], p, bA.y);
            fma2(acc2[1][2], p, bB.x); fma2(acc2[1][3], p, bB.y);
            p = pack2(a0.z);
            fma2(acc2[2][0], p, bA.x); fma2(acc2[2][1], p, bA.y);
            fma2(acc2[2][2], p, bB.x); fma2(acc2[2][3], p, bB.y);
            p = pack2(a0.w);
            fma2(acc2[3][0], p, bA.x); fma2(acc2[3][1], p, bA.y);
            fma2(acc2[3][2], p, bB.x); fma2(acc2[3][3], p, bB.y);
            p = pack2(a1.x);
            fma2(acc2[4][0], p, bA.x); fma2(acc2[4][1], p, bA.y);
            fma2(acc2[4][2], p, bB.x); fma2(acc2[4][3], p, bB.y);
            p = pack2(a1.y);
            fma2(acc2[5][0], p, bA.x); fma2(acc2[5][1], p, bA.y);
            fma2(acc2[5][2], p, bB.x); fma2(acc2[5][3], p, bB.y);
            p = pack2(a1.z);
            fma2(acc2[6][0], p, bA.x); fma2(acc2[6][1], p, bA.y);
            fma2(acc2[6][2], p, bB.x); fma2(acc2[6][3], p, bB.y);
            p = pack2(a1.w);
            fma2(acc2[7][0], p, bA.x); fma2(acc2[7][1], p, bA.y);
            fma2(acc2[7][2], p, bB.x); fma2(acc2[7][3], p, bB.y);
        }
    }

#pragma unroll
    for (int i = 0; i < 8; i++) {
        float* crow = C + (size_t)(mb + ty * 8 + i) * G4 + (nb + tx * 8);
        float2 c0 = unpack2(acc2[i][0]);
        float2 c1 = unpack2(acc2[i][1]);
        float2 c2 = unpack2(acc2[i][2]);
        float2 c3 = unpack2(acc2[i][3]);
        float4 v0 = make_float4(c0.x + biasr[0], c0.y + biasr[1],
                                c1.x + biasr[2], c1.y + biasr[3]);
        float4 v1 = make_float4(c2.x + biasr[4], c2.y + biasr[5],
                                c3.x + biasr[6], c3.y + biasr[7]);
        *(float4*)crow = v0;
        *(float4*)(crow + 4) = v1;
    }
}

// ---------------- recurrent persistent kernel ------------------------------
#define SMEM_REC (64 * 256 * 4 + 36 * 256 * 4)   // Bs + padded h tile = 100 KB

__global__ void __launch_bounds__(128) k_lstm(
    const float* __restrict__ Whh, const int* __restrict__ lengths,
    float* __restrict__ dout, int layer)
{
    extern __shared__ float sm[];
    float* Bs = sm;                 // [256][64]  weights, n' = ulocal*4+g
    float* Ah = sm + 64 * 256;      // [256][36]  h tile (padded)

    const int bx  = blockIdx.x;
    const int dir = bx >> 6;
    const int cta = bx & 63;
    const int bg  = cta >> 4;           // batch group 0..3
    const int hsI = cta & 15;           // hidden slice 0..15
    const int bb  = bg * 32;
    const int hb  = hsI * 16;
    const int tid = threadIdx.x;
    const int tx  = tid & 15, ty = tid >> 4;   // ty 0..7

    const float* W = Whh + (size_t)(layer * 2 + dir) * G4 * HH;

    // resident weight load (once per launch)
    for (int idx = tid; idx < 64 * 256; idx += 128) {
        int nl = idx >> 8; int k = idx & 255;
        int row = (nl & 3) * HH + hb + (nl >> 2);
        Bs[k * 64 + nl] = W[(size_t)row * HH + k];
    }

    const int u = hb + tx;
    int lenr[4];
#pragma unroll
    for (int i = 0; i < 4; i++) {
        int b = bb + ty * 4 + i;
        lenr[i] = lengths[b];
        g_hbuf[0][dir][b][u] = 0.f;     // zero parity-0 h
    }
    float cs[4] = {0.f, 0.f, 0.f, 0.f};
    float hs[4] = {0.f, 0.f, 0.f, 0.f};

    if (tid == 0) g_flag[dir][bg][hsI] = 0;   // reset flags (graph-replay safe)

    gridbar();   // one global barrier: zeroed h + reset flags visible everywhere

    const int bl = tid >> 2;            // 0..31 (batch row for staging)
    const int kc = (tid & 3) * 64;      // k chunk for staging

    const float* xpbase = g_xproj + (size_t)dir * TT * BB * G4;

    // prefetch xproj gates for first step
    float4 pg[4];
    {
        int t0 = dir ? (TT - 1) : 0;
#pragma unroll
        for (int i = 0; i < 4; i++)
            pg[i] = *(const float4*)(xpbase + ((size_t)t0 * BB + bb + ty * 4 + i) * G4
                                     + (size_t)u * 4);
    }

    for (int s = 0; s < TT; s++) {
        int t = dir ? (TT - 1 - s) : s;
        int p = s & 1;

        // group-scope wait: our 16 producers must have finished step s-1
        if (tid < 16) {
            const unsigned* fp = &g_flag[dir][bg][tid];
            while (ld_acq(fp) < (unsigned)s) { }
        }
        __syncthreads();

        // stage h tile: global (L2) -> smem transposed [k][m]
        const float* hsrc = &g_hbuf[p][dir][bb + bl][kc];
#pragma unroll
        for (int i = 0; i < 16; i++) {
            float4 v = __ldcg((const float4*)(hsrc + i * 4));
            int k0 = kc + i * 4;
            Ah[(k0 + 0) * 36 + bl] = v.x;
            Ah[(k0 + 1) * 36 + bl] = v.y;
            Ah[(k0 + 2) * 36 + bl] = v.z;
            Ah[(k0 + 3) * 36 + bl] = v.w;
        }
        __syncthreads();

        unsigned long long acc2[4][2];
#pragma unroll
        for (int i = 0; i < 4; i++) { acc2[i][0] = 0ULL; acc2[i][1] = 0ULL; }

#pragma unroll 8
        for (int k = 0; k < HH; k++) {
            float4 a  = *(const float4*)&Ah[k * 36 + (ty << 2)];
            ulonglong2 bq = *(const ulonglong2*)&Bs[(k << 6) + (tx << 2)];
            unsigned long long ax = pack2(a.x), ay = pack2(a.y);
            unsigned long long az = pack2(a.z), aw = pack2(a.w);
            fma2(acc2[0][0], ax, bq.x); fma2(acc2[0][1], ax, bq.y);
            fma2(acc2[1][0], ay, bq.x); fma2(acc2[1][1], ay, bq.y);
            fma2(acc2[2][0], az, bq.x); fma2(acc2[2][1], az, bq.y);
            fma2(acc2[3][0], aw, bq.x); fma2(acc2[3][1], aw, bq.y);
        }

#pragma unroll
        for (int i = 0; i < 4; i++) {
            float2 cif = unpack2(acc2[i][0]);    // gates i, f
            float2 cgo = unpack2(acc2[i][1]);    // gates g, o
            float4 g = pg[i];
            float gi = sigmfast(cif.x + g.x);
            float gf = sigmfast(cif.y + g.y);
            float gg = tanhfast(cgo.x + g.z);
            float go = sigmfast(cgo.y + g.w);
            float cn = gf * cs[i] + gi * gg;
            float hn = go * tanhfast(cn);
            bool val = (t < lenr[i]);
            if (val) { cs[i] = cn; hs[i] = hn; }
            float ov = val ? hn : 0.f;
            int b = bb + ty * 4 + i;
            if (layer == 0)
                g_inp2[((size_t)t * BB + b) * 512 + dir * HH + u] = ov;
            else
                dout[((size_t)b * TT + t) * 512 + dir * HH + u] = ov;
            __stcg(&g_hbuf[1 - p][dir][b][u], hs[i]);
        }

        __syncthreads();               // all h stores of this CTA done
        if (tid == 0) {
            __threadfence();           // publish them at gpu scope
            st_rel(&g_flag[dir][bg][hsI], (unsigned)(s + 1));
        }

        // prefetch next step's gates (overlaps the next flag wait)
        if (s + 1 < TT) {
            int t2 = dir ? (TT - 2 - s) : (s + 1);
#pragma unroll
            for (int i = 0; i < 4; i++)
                pg[i] = *(const float4*)(xpbase + ((size_t)t2 * BB + bb + ty * 4 + i) * G4
                                         + (size_t)u * 4);
        }
    }

    // final h_n / c_n
#pragma unroll
    for (int i = 0; i < 4; i++) {
        int b = bb + ty * 4 + i;
        size_t o = (size_t)((layer * 2 + dir) * BB + b) * HH + u;
        dout[HN_OFF + o] = hs[i];
        dout[CN_OFF + o] = cs[i];
    }
}

// ---------------- launch -----------------------------------------------------
extern "C" void kernel_launch(void* const* d_in, const int* in_sizes, int n_in,
                              void* d_out, int out_size)
{
    const float* x   = (const float*)d_in[0];
    const int*   len = (const int*)d_in[1];
    const float* Wih = (const float*)d_in[2];
    const float* Whh = (const float*)d_in[3];
    const float* bih = (const float*)d_in[4];
    const float* bhh = (const float*)d_in[5];
    float* out = (float*)d_out;

    cudaFuncSetAttribute(k_lstm, cudaFuncAttributeMaxDynamicSharedMemorySize, SMEM_REC);

    // transpose x -> (T,B,D)
    {
        int n4 = TT * BB * (DIN / 4);
        k_transpose<<<(n4 + 1023) / 1024, 1024>>>(x);
    }
    // layer 0
    k_gemm_xproj<<<dim3(8, 512, 2), 256>>>(Wih, bih, bhh, 0);
    k_lstm<<<NBLK, 128, SMEM_REC>>>(Whh, len, out, 0);
    // layer 1
    k_gemm_xproj<<<dim3(8, 512, 2), 256>>>(Wih, bih, bhh, 1);
    k_lstm<<<NBLK, 128, SMEM_REC>>>(Whh, len, out, 1);
}

// round 4
// speedup vs baseline: 1.2434x; 1.1049x over previous
#include <cuda_runtime.h>
#include <cuda_bf16.h>
#include <cstdint>

#define BB   128      // batch
#define TT   512      // time
#define DIN  512      // input dim (also 2H for layer 1)
#define HH   256      // hidden
#define G4   1024     // 4*H
#define NBLK 128      // recurrent grid size
#define MM   (TT*BB)  // 65536 rows of A

#define HN_OFF 33554432ULL              // B*T*512
#define CN_OFF (HN_OFF + 131072ULL)     // + 4*B*H

// ---------------- device scratch (static, no runtime alloc) ----------------
__device__ __align__(256) __nv_bfloat16 g_xh[(size_t)MM * DIN];   // x hi (T,B,D)
__device__ __align__(256) __nv_bfloat16 g_xl[(size_t)MM * DIN];   // x lo
__device__ __align__(256) __nv_bfloat16 g_i2h[(size_t)MM * DIN];  // layer-1 input hi
__device__ __align__(256) __nv_bfloat16 g_i2l[(size_t)MM * DIN];  // layer-1 input lo
__device__ __align__(256) __nv_bfloat16 g_wh[4ULL * G4 * DIN];    // permuted W_ih hi
__device__ __align__(256) __nv_bfloat16 g_wl[4ULL * G4 * DIN];    // permuted W_ih lo
__device__ __align__(256) float g_bias[4 * G4];                   // permuted b_ih+b_hh
__device__ __align__(256) float g_xproj[2ULL * TT * BB * G4];     // gate preacts
__device__ __align__(256) float g_hbuf[2][2][BB][HH];             // parity, dir
__device__ unsigned g_flag[2][4][16];                             // dir, bgroup, hslice
__device__ unsigned long long g_bar = 0ULL;

// ---------------- small helpers --------------------------------------------
__device__ __forceinline__ float tanhfast(float x) {
    float y; asm("tanh.approx.f32 %0, %1;" : "=f"(y) : "f"(x)); return y;
}
__device__ __forceinline__ float sigmfast(float x) {
    return fmaf(0.5f, tanhfast(0.5f * x), 0.5f);
}
__device__ __forceinline__ unsigned ld_acq(const unsigned* p) {
    unsigned v; asm volatile("ld.acquire.gpu.u32 %0, [%1];" : "=r"(v) : "l"(p)); return v;
}
__device__ __forceinline__ void st_rel(unsigned* p, unsigned v) {
    asm volatile("st.release.gpu.u32 [%0], %1;" :: "l"(p), "r"(v));
}
__device__ __forceinline__ uint32_t smem_u32(const void* p) {
    uint32_t a;
    asm("{ .reg .u64 t; cvta.to.shared.u64 t, %1; cvt.u32.u64 %0, t; }" : "=r"(a) : "l"(p));
    return a;
}
__device__ __forceinline__ void split_bf16(float v, __nv_bfloat16& h, __nv_bfloat16& l) {
    h = __float2bfloat16(v);
    l = __float2bfloat16(v - __bfloat162float(h));
}

// ---------------- mma.sync / ldmatrix / cp.async wrappers -------------------
__device__ __forceinline__ void ldm4(uint32_t* r, uint32_t addr) {
    asm volatile("ldmatrix.sync.aligned.m8n8.x4.shared.b16 {%0,%1,%2,%3}, [%4];"
                 : "=r"(r[0]), "=r"(r[1]), "=r"(r[2]), "=r"(r[3]) : "r"(addr));
}
__device__ __forceinline__ void mma_bf16(float* d, const uint32_t* a,
                                         uint32_t b0, uint32_t b1) {
    asm volatile(
        "mma.sync.aligned.m16n8k16.row.col.f32.bf16.bf16.f32 "
        "{%0,%1,%2,%3}, {%4,%5,%6,%7}, {%8,%9}, {%0,%1,%2,%3};"
        : "+f"(d[0]), "+f"(d[1]), "+f"(d[2]), "+f"(d[3])
        : "r"(a[0]), "r"(a[1]), "r"(a[2]), "r"(a[3]), "r"(b0), "r"(b1));
}
__device__ __forceinline__ void cpasync16(uint32_t dst, const void* src) {
    asm volatile("cp.async.cg.shared.global [%0], [%1], 16;" :: "r"(dst), "l"(src));
}
#define CP_COMMIT() asm volatile("cp.async.commit_group;" ::: "memory")
#define CP_WAIT(n)  asm volatile("cp.async.wait_group %0;" :: "n"(n) : "memory")

// ---------------- global barrier (monotonic, once per lstm launch) ----------
__device__ __forceinline__ void gridbar()
{
    __syncthreads();
    if (threadIdx.x == 0) {
        __threadfence();
        unsigned long long t = atomicAdd(&g_bar, 1ULL) + 1ULL;
        unsigned long long target = ((t + NBLK - 1ULL) / NBLK) * NBLK;
        while (atomicAdd(&g_bar, 0ULL) < target) { __nanosleep(64); }
        __threadfence();
    }
    __syncthreads();
}

// ---------------- split + transpose x: (B,T,D) fp32 -> (T,B,D) bf16 hi/lo ---
__global__ void k_split_x(const float* __restrict__ x)
{
    int i = blockIdx.x * blockDim.x + threadIdx.x;       // float4 index
    const int N4 = MM * (DIN / 4);
    if (i >= N4) return;
    int k4 = i & 127;
    int bt = i >> 7;
    int t = bt & (TT - 1);
    int b = bt >> 9;
    float4 v = ((const float4*)x)[i];
    __nv_bfloat16 h[4], l[4];
    split_bf16(v.x, h[0], l[0]); split_bf16(v.y, h[1], l[1]);
    split_bf16(v.z, h[2], l[2]); split_bf16(v.w, h[3], l[3]);
    size_t off = ((size_t)t * BB + b) * DIN + k4 * 4;
    *(uint2*)(g_xh + off) = *(uint2*)h;
    *(uint2*)(g_xl + off) = *(uint2*)l;
}

// ---------------- split + permute weights ----------------------------------
__global__ void k_split_w(const float* __restrict__ Wih, const float* __restrict__ bih,
                          const float* __restrict__ bhh)
{
    int i = blockIdx.x * blockDim.x + threadIdx.x;       // (ld, n, k4)
    if (i >= 4 * G4 * (DIN / 4)) return;
    int k4 = i & 127;
    int rest = i >> 7;
    int n = rest & (G4 - 1);
    int ld = rest >> 10;
    int r = (n & 3) * HH + (n >> 2);
    float4 v = *(const float4*)(Wih + ((size_t)ld * G4 + r) * DIN + k4 * 4);
    __nv_bfloat16 h[4], l[4];
    split_bf16(v.x, h[0], l[0]); split_bf16(v.y, h[1], l[1]);
    split_bf16(v.z, h[2], l[2]); split_bf16(v.w, h[3], l[3]);
    size_t off = ((size_t)ld * G4 + n) * DIN + k4 * 4;
    *(uint2*)(g_wh + off) = *(uint2*)h;
    *(uint2*)(g_wl + off) = *(uint2*)l;
    if (k4 == 0)
        g_bias[ld * G4 + n] = bih[ld * G4 + r] + bhh[ld * G4 + r];
}

// ---------------- mma.sync input-projection GEMM -----------------------------
// C[dir][m][n'] = sum_k A[m][k]*Wp[dir][n'][k] + bias[n'],  bf16 hi/lo 3-term
#define KC     32
#define LDS_T  40                          // padded row (bf16 elems)
#define ARR_B  (128 * LDS_T * 2)           // 10240 bytes per array
#define STG_B  (4 * ARR_B)                 // 40960 bytes per stage
#define SMO_BIAS  0
#define SMO_TILES 512
#define SM_GEMM   (SMO_TILES + 2 * STG_B)  // 82432

__global__ void __launch_bounds__(256, 1) k_gemm_tc(int layer)
{
    extern __shared__ char smx[];
    const uint32_t smb = smem_u32(smx);
    const int tid = threadIdx.x;
    const int lane = tid & 31;
    const int w   = tid >> 5;             // 0..7
    const int wm  = w & 1;                // M: 2 x 64
    const int wn  = w >> 1;               // N: 4 x 32
    const int dir = blockIdx.z;
    const int mb  = blockIdx.y * 128;
    const int nb  = blockIdx.x * 128;

    const __nv_bfloat16* Ah = layer ? g_i2h : g_xh;
    const __nv_bfloat16* Al = layer ? g_i2l : g_xl;
    const __nv_bfloat16* Wh = g_wh + (size_t)(layer * 2 + dir) * G4 * DIN;
    const __nv_bfloat16* Wl = g_wl + (size_t)(layer * 2 + dir) * G4 * DIN;

    float* bs = (float*)(smx + SMO_BIAS);
    if (tid < 128) bs[tid] = g_bias[(layer * 2 + dir) * G4 + nb + tid];

    // copy-index decomposition for one stage (2048 x 16B)
    const int crow[8] = {0,0,0,0,0,0,0,0};   // placeholder to keep arrays local
    (void)crow;

    // issue stage 0
    {
        const int kc = 0;
#pragma unroll
        for (int j = 0; j < 8; j++) {
            int c = tid + j * 256;
            int arr = c >> 9, rem = c & 511, row = rem >> 2, ck = rem & 3;
            uint32_t dst = smb + SMO_TILES + arr * ARR_B + row * (LDS_T * 2) + ck * 16;
            const __nv_bfloat16* src;
            if (arr == 0)      src = Ah + (size_t)(mb + row) * DIN + kc + ck * 8;
            else if (arr == 1) src = Al + (size_t)(mb + row) * DIN + kc + ck * 8;
            else if (arr == 2) src = Wh + (size_t)(nb + row) * DIN + kc + ck * 8;
            else               src = Wl + (size_t)(nb + row) * DIN + kc + ck * 8;
            cpasync16(dst, src);
        }
        CP_COMMIT();
    }

    float acc[4][4][4];
#pragma unroll
    for (int mi = 0; mi < 4; mi++)
#pragma unroll
        for (int ni = 0; ni < 4; ni++)
#pragma unroll
            for (int q = 0; q < 4; q++) acc[mi][ni][q] = 0.f;

    for (int ch = 0; ch < DIN / KC; ch++) {
        // prefetch next stage
        if (ch + 1 < DIN / KC) {
            const int kc = (ch + 1) * KC;
            const uint32_t sb = smb + SMO_TILES + ((ch + 1) & 1) * STG_B;
#pragma unroll
            for (int j = 0; j < 8; j++) {
                int c = tid + j * 256;
                int arr = c >> 9, rem = c & 511, row = rem >> 2, ck = rem & 3;
                uint32_t dst = sb + arr * ARR_B + row * (LDS_T * 2) + ck * 16;
                const __nv_bfloat16* src;
                if (arr == 0)      src = Ah + (size_t)(mb + row) * DIN + kc + ck * 8;
                else if (arr == 1) src = Al + (size_t)(mb + row) * DIN + kc + ck * 8;
                else if (arr == 2) src = Wh + (size_t)(nb + row) * DIN + kc + ck * 8;
                else               src = Wl + (size_t)(nb + row) * DIN + kc + ck * 8;
                cpasync16(dst, src);
            }
            CP_COMMIT();
            CP_WAIT(1);
        } else {
            CP_WAIT(0);
        }
        __syncthreads();

        const uint32_t sA_h = smb + SMO_TILES + (ch & 1) * STG_B;
        const uint32_t sA_l = sA_h + ARR_B;
        const uint32_t sB_h = sA_h + 2 * ARR_B;
        const uint32_t sB_l = sA_h + 3 * ARR_B;

#pragma unroll
        for (int ks = 0; ks < 2; ks++) {
            const int k0 = ks * 16;
            const uint32_t aoff = ((lane & 15) * LDS_T + k0 + (lane >> 4) * 8) * 2;
            uint32_t ah[4][4], al[4][4];
#pragma unroll
            for (int mi = 0; mi < 4; mi++) {
                uint32_t ro = (wm * 64 + mi * 16) * (LDS_T * 2);
                ldm4(ah[mi], sA_h + ro + aoff);
                ldm4(al[mi], sA_l + ro + aoff);
            }
            uint32_t bh[2][4], bl[2][4];
#pragma unroll
            for (int nj = 0; nj < 2; nj++) {
                uint32_t ro = (wn * 32 + nj * 16) * (LDS_T * 2);
                ldm4(bh[nj], sB_h + ro + aoff);
                ldm4(bl[nj], sB_l + ro + aoff);
            }
#pragma unroll
            for (int mi = 0; mi < 4; mi++)
#pragma unroll
                for (int ni = 0; ni < 4; ni++) {
                    int nj = ni >> 1, hf = ni & 1;
                    mma_bf16(acc[mi][ni], ah[mi], bh[nj][hf], bh[nj][hf + 2]);
                    mma_bf16(acc[mi][ni], ah[mi], bl[nj][hf], bl[nj][hf + 2]);
                    mma_bf16(acc[mi][ni], al[mi], bh[nj][hf], bh[nj][hf + 2]);
                }
        }
        __syncthreads();
    }

    // ---- epilogue: registers -> global fp32 with fused bias ----
    float* xp = g_xproj + (size_t)dir * TT * BB * G4;
    const int gid = lane >> 2, tig = lane & 3;
#pragma unroll
    for (int mi = 0; mi < 4; mi++) {
#pragma unroll
        for (int ni = 0; ni < 4; ni++) {
            int col = wn * 32 + ni * 8 + tig * 2;
            float b0 = bs[col], b1 = bs[col + 1];
            int r0 = mb + wm * 64 + mi * 16 + gid;
            float2 v0 = make_float2(acc[mi][ni][0] + b0, acc[mi][ni][1] + b1);
            float2 v1 = make_float2(acc[mi][ni][2] + b0, acc[mi][ni][3] + b1);
            *(float2*)(xp + (size_t)r0 * G4 + nb + col) = v0;
            *(float2*)(xp + (size_t)(r0 + 8) * G4 + nb + col) = v1;
        }
    }
}

// ---------------- recurrent persistent kernel ------------------------------
#define SMEM_REC (64 * 256 * 4 + 36 * 256 * 4)   // Bs + padded h tile = 100 KB

__global__ void __launch_bounds__(128) k_lstm(
    const float* __restrict__ Whh, const int* __restrict__ lengths,
    float* __restrict__ dout, int layer)
{
    extern __shared__ float sm[];
    float* Bs = sm;                 // [256][64]  weights, n' = ulocal*4+g
    float* Ahs = sm + 64 * 256;     // [256][36]  h tile (padded)

    const int bx  = blockIdx.x;
    const int dir = bx >> 6;
    const int cta = bx & 63;
    const int bg  = cta >> 4;
    const int hsI = cta & 15;
    const int bb  = bg * 32;
    const int hb  = hsI * 16;
    const int tid = threadIdx.x;
    const int tx  = tid & 15, ty = tid >> 4;

    const float* W = Whh + (size_t)(layer * 2 + dir) * G4 * HH;

    for (int idx = tid; idx < 64 * 256; idx += 128) {
        int nl = idx >> 8; int k = idx & 255;
        int row = (nl & 3) * HH + hb + (nl >> 2);
        Bs[k * 64 + nl] = W[(size_t)row * HH + k];
    }

    const int u = hb + tx;
    int lenr[4];
#pragma unroll
    for (int i = 0; i < 4; i++) {
        int b = bb + ty * 4 + i;
        lenr[i] = lengths[b];
        g_hbuf[0][dir][b][u] = 0.f;
    }
    float cs[4] = {0.f, 0.f, 0.f, 0.f};
    float hs[4] = {0.f, 0.f, 0.f, 0.f};

    if (tid == 0) g_flag[dir][bg][hsI] = 0;

    gridbar();

    const int bl = tid >> 2;
    const int kc = (tid & 3) * 64;
    const float* xpbase = g_xproj + (size_t)dir * TT * BB * G4;

    float4 pg[4];
    {
        int t0 = dir ? (TT - 1) : 0;
#pragma unroll
        for (int i = 0; i < 4; i++)
            pg[i] = *(const float4*)(xpbase + ((size_t)t0 * BB + bb + ty * 4 + i) * G4
                                     + (size_t)u * 4);
    }

    for (int s = 0; s < TT; s++) {
        int t = dir ? (TT - 1 - s) : s;
        int p = s & 1;

        if (tid < 16) {
            const unsigned* fp = &g_flag[dir][bg][tid];
            while (ld_acq(fp) < (unsigned)s) { }
        }
        __syncthreads();

        const float* hsrc = &g_hbuf[p][dir][bb + bl][kc];
#pragma unroll
        for (int i = 0; i < 16; i++) {
            float4 v = __ldcg((const float4*)(hsrc + i * 4));
            int k0 = kc + i * 4;
            Ahs[(k0 + 0) * 36 + bl] = v.x;
            Ahs[(k0 + 1) * 36 + bl] = v.y;
            Ahs[(k0 + 2) * 36 + bl] = v.z;
            Ahs[(k0 + 3) * 36 + bl] = v.w;
        }
        __syncthreads();

        float acc[4][4];
#pragma unroll
        for (int i = 0; i < 4; i++)
#pragma unroll
            for (int j = 0; j < 4; j++) acc[i][j] = 0.f;

#pragma unroll 8
        for (int k = 0; k < HH; k++) {
            float4 a  = *(const float4*)&Ahs[k * 36 + (ty << 2)];
            float4 b4 = *(const float4*)&Bs[(k << 6) + (tx << 2)];
            acc[0][0] += a.x * b4.x; acc[0][1] += a.x * b4.y;
            acc[0][2] += a.x * b4.z; acc[0][3] += a.x * b4.w;
            acc[1][0] += a.y * b4.x; acc[1][1] += a.y * b4.y;
            acc[1][2] += a.y * b4.z; acc[1][3] += a.y * b4.w;
            acc[2][0] += a.z * b4.x; acc[2][1] += a.z * b4.y;
            acc[2][2] += a.z * b4.z; acc[2][3] += a.z * b4.w;
            acc[3][0] += a.w * b4.x; acc[3][1] += a.w * b4.y;
            acc[3][2] += a.w * b4.z; acc[3][3] += a.w * b4.w;
        }

#pragma unroll
        for (int i = 0; i < 4; i++) {
            float4 g = pg[i];
            float gi = sigmfast(acc[i][0] + g.x);
            float gf = sigmfast(acc[i][1] + g.y);
            float gg = tanhfast(acc[i][2] + g.z);
            float go = sigmfast(acc[i][3] + g.w);
            float cn = gf * cs[i] + gi * gg;
            float hn = go * tanhfast(cn);
            bool val = (t < lenr[i]);
            if (val) { cs[i] = cn; hs[i] = hn; }
            float ov = val ? hn : 0.f;
            int b = bb + ty * 4 + i;
            if (layer == 0) {
                __nv_bfloat16 h16, l16;
                split_bf16(ov, h16, l16);
                size_t off = ((size_t)t * BB + b) * DIN + dir * HH + u;
                g_i2h[off] = h16;
                g_i2l[off] = l16;
            } else {
                dout[((size_t)b * TT + t) * 512 + dir * HH + u] = ov;
            }
            __stcg(&g_hbuf[1 - p][dir][b][u], hs[i]);
        }

        __syncthreads();
        if (tid == 0) {
            __threadfence();
            st_rel(&g_flag[dir][bg][hsI], (unsigned)(s + 1));
        }

        if (s + 1 < TT) {
            int t2 = dir ? (TT - 2 - s) : (s + 1);
#pragma unroll
            for (int i = 0; i < 4; i++)
                pg[i] = *(const float4*)(xpbase + ((size_t)t2 * BB + bb + ty * 4 + i) * G4
                                         + (size_t)u * 4);
        }
    }

#pragma unroll
    for (int i = 0; i < 4; i++) {
        int b = bb + ty * 4 + i;
        size_t o = (size_t)((layer * 2 + dir) * BB + b) * HH + u;
        dout[HN_OFF + o] = hs[i];
        dout[CN_OFF + o] = cs[i];
    }
}

// ---------------- launch -----------------------------------------------------
extern "C" void kernel_launch(void* const* d_in, const int* in_sizes, int n_in,
                              void* d_out, int out_size)
{
    const float* x   = (const float*)d_in[0];
    const int*   len = (const int*)d_in[1];
    const float* Wih = (const float*)d_in[2];
    const float* Whh = (const float*)d_in[3];
    const float* bih = (const float*)d_in[4];
    const float* bhh = (const float*)d_in[5];
    float* out = (float*)d_out;

    cudaFuncSetAttribute(k_lstm, cudaFuncAttributeMaxDynamicSharedMemorySize, SMEM_REC);
    cudaFuncSetAttribute(k_gemm_tc, cudaFuncAttributeMaxDynamicSharedMemorySize, SM_GEMM);

    k_split_x<<<(MM * (DIN / 4) + 255) / 256, 256>>>(x);
    k_split_w<<<(4 * G4 * (DIN / 4) + 255) / 256, 256>>>(Wih, bih, bhh);

    k_gemm_tc<<<dim3(G4 / 128, MM / 128, 2), 256, SM_GEMM>>>(0);
    k_lstm<<<NBLK, 128, SMEM_REC>>>(Whh, len, out, 0);
    k_gemm_tc<<<dim3(G4 / 128, MM / 128, 2), 256, SM_GEMM>>>(1);
    k_lstm<<<NBLK, 128, SMEM_REC>>>(Whh, len, out, 1);
}

// round 5
// speedup vs baseline: 1.8756x; 1.5084x over previous
#include <cuda_runtime.h>
#include <cuda_bf16.h>
#include <cstdint>

#define BB   128      // batch
#define TT   512      // time
#define DIN  512      // input dim (also 2H for layer 1)
#define HH   256      // hidden
#define G4   1024     // 4*H
#define NBLK 128      // recurrent grid size
#define MM   (TT*BB)  // 65536 rows of A

#define HN_OFF 33554432ULL              // B*T*512
#define CN_OFF (HN_OFF + 131072ULL)     // + 4*B*H

// ---------------- device scratch (static, no runtime alloc) ----------------
__device__ __align__(256) __nv_bfloat16 g_xh[(size_t)MM * DIN];   // x hi (T,B,D)
__device__ __align__(256) __nv_bfloat16 g_xl[(size_t)MM * DIN];   // x lo
__device__ __align__(256) __nv_bfloat16 g_i2h[(size_t)MM * DIN];  // layer-1 input hi
__device__ __align__(256) __nv_bfloat16 g_i2l[(size_t)MM * DIN];  // layer-1 input lo
__device__ __align__(256) __nv_bfloat16 g_wh[4ULL * G4 * DIN];    // permuted W_ih hi
__device__ __align__(256) __nv_bfloat16 g_wl[4ULL * G4 * DIN];    // permuted W_ih lo
__device__ __align__(256) float g_bias[4 * G4];                   // permuted b_ih+b_hh
__device__ __align__(256) float g_xproj[2ULL * TT * BB * G4];     // gate preacts
__device__ __align__(256) uint32_t g_hx[2][2][BB][HH];            // packed h (hi|lo<<16)
__device__ unsigned g_flag[2][4][16];                             // dir, bgroup, nslice
__device__ unsigned long long g_bar = 0ULL;

// ---------------- small helpers --------------------------------------------
__device__ __forceinline__ float tanhfast(float x) {
    float y; asm("tanh.approx.f32 %0, %1;" : "=f"(y) : "f"(x)); return y;
}
__device__ __forceinline__ float sigmfast(float x) {
    return fmaf(0.5f, tanhfast(0.5f * x), 0.5f);
}
__device__ __forceinline__ unsigned ld_acq(const unsigned* p) {
    unsigned v; asm volatile("ld.acquire.gpu.u32 %0, [%1];" : "=r"(v) : "l"(p)); return v;
}
__device__ __forceinline__ void st_rel(unsigned* p, unsigned v) {
    asm volatile("st.release.gpu.u32 [%0], %1;" :: "l"(p), "r"(v));
}
__device__ __forceinline__ uint32_t smem_u32(const void* p) {
    uint32_t a;
    asm("{ .reg .u64 t; cvta.to.shared.u64 t, %1; cvt.u32.u64 %0, t; }" : "=r"(a) : "l"(p));
    return a;
}
__device__ __forceinline__ void split_bf16(float v, __nv_bfloat16& h, __nv_bfloat16& l) {
    h = __float2bfloat16(v);
    l = __float2bfloat16(v - __bfloat162float(h));
}
__device__ __forceinline__ uint32_t pack_hl(float v) {
    __nv_bfloat16 h, l;
    split_bf16(v, h, l);
    return (uint32_t)__bfloat16_as_ushort(h) | ((uint32_t)__bfloat16_as_ushort(l) << 16);
}

// ---------------- mma.sync / ldmatrix / cp.async wrappers -------------------
__device__ __forceinline__ void ldm4(uint32_t* r, uint32_t addr) {
    asm volatile("ldmatrix.sync.aligned.m8n8.x4.shared.b16 {%0,%1,%2,%3}, [%4];"
                 : "=r"(r[0]), "=r"(r[1]), "=r"(r[2]), "=r"(r[3]) : "r"(addr));
}
__device__ __forceinline__ void mma_bf16(float* d, const uint32_t* a,
                                         uint32_t b0, uint32_t b1) {
    asm volatile(
        "mma.sync.aligned.m16n8k16.row.col.f32.bf16.bf16.f32 "
        "{%0,%1,%2,%3}, {%4,%5,%6,%7}, {%8,%9}, {%0,%1,%2,%3};"
        : "+f"(d[0]), "+f"(d[1]), "+f"(d[2]), "+f"(d[3])
        : "r"(a[0]), "r"(a[1]), "r"(a[2]), "r"(a[3]), "r"(b0), "r"(b1));
}
__device__ __forceinline__ void cpasync16(uint32_t dst, const void* src) {
    asm volatile("cp.async.cg.shared.global [%0], [%1], 16;" :: "r"(dst), "l"(src));
}
#define CP_COMMIT() asm volatile("cp.async.commit_group;" ::: "memory")
#define CP_WAIT(n)  asm volatile("cp.async.wait_group %0;" :: "n"(n) : "memory")

// ---------------- global barrier (monotonic, once per lstm launch) ----------
__device__ __forceinline__ void gridbar()
{
    __syncthreads();
    if (threadIdx.x == 0) {
        __threadfence();
        unsigned long long t = atomicAdd(&g_bar, 1ULL) + 1ULL;
        unsigned long long target = ((t + NBLK - 1ULL) / NBLK) * NBLK;
        while (atomicAdd(&g_bar, 0ULL) < target) { __nanosleep(64); }
        __threadfence();
    }
    __syncthreads();
}

// ---------------- split + transpose x: (B,T,D) fp32 -> (T,B,D) bf16 hi/lo ---
__global__ void k_split_x(const float* __restrict__ x)
{
    int i = blockIdx.x * blockDim.x + threadIdx.x;       // float4 index
    const int N4 = MM * (DIN / 4);
    if (i >= N4) return;
    int k4 = i & 127;
    int bt = i >> 7;
    int t = bt & (TT - 1);
    int b = bt >> 9;
    float4 v = ((const float4*)x)[i];
    __nv_bfloat16 h[4], l[4];
    split_bf16(v.x, h[0], l[0]); split_bf16(v.y, h[1], l[1]);
    split_bf16(v.z, h[2], l[2]); split_bf16(v.w, h[3], l[3]);
    size_t off = ((size_t)t * BB + b) * DIN + k4 * 4;
    *(uint2*)(g_xh + off) = *(uint2*)h;
    *(uint2*)(g_xl + off) = *(uint2*)l;
}

// ---------------- split + permute weights ----------------------------------
__global__ void k_split_w(const float* __restrict__ Wih, const float* __restrict__ bih,
                          const float* __restrict__ bhh)
{
    int i = blockIdx.x * blockDim.x + threadIdx.x;       // (ld, n, k4)
    if (i >= 4 * G4 * (DIN / 4)) return;
    int k4 = i & 127;
    int rest = i >> 7;
    int n = rest & (G4 - 1);
    int ld = rest >> 10;
    int r = (n & 3) * HH + (n >> 2);
    float4 v = *(const float4*)(Wih + ((size_t)ld * G4 + r) * DIN + k4 * 4);
    __nv_bfloat16 h[4], l[4];
    split_bf16(v.x, h[0], l[0]); split_bf16(v.y, h[1], l[1]);
    split_bf16(v.z, h[2], l[2]); split_bf16(v.w, h[3], l[3]);
    size_t off = ((size_t)ld * G4 + n) * DIN + k4 * 4;
    *(uint2*)(g_wh + off) = *(uint2*)h;
    *(uint2*)(g_wl + off) = *(uint2*)l;
    if (k4 == 0)
        g_bias[ld * G4 + n] = bih[ld * G4 + r] + bhh[ld * G4 + r];
}

// ---------------- mma.sync input-projection GEMM -----------------------------
#define KC     32
#define LDS_T  40
#define ARR_B  (128 * LDS_T * 2)
#define STG_B  (4 * ARR_B)
#define SMO_BIAS  0
#define SMO_TILES 512
#define SM_GEMM   (SMO_TILES + 2 * STG_B)

__global__ void __launch_bounds__(256, 1) k_gemm_tc(int layer)
{
    extern __shared__ char smx[];
    const uint32_t smb = smem_u32(smx);
    const int tid = threadIdx.x;
    const int lane = tid & 31;
    const int w   = tid >> 5;
    const int wm  = w & 1;
    const int wn  = w >> 1;
    const int dir = blockIdx.z;
    const int mb  = blockIdx.y * 128;
    const int nb  = blockIdx.x * 128;

    const __nv_bfloat16* Ah = layer ? g_i2h : g_xh;
    const __nv_bfloat16* Al = layer ? g_i2l : g_xl;
    const __nv_bfloat16* Wh = g_wh + (size_t)(layer * 2 + dir) * G4 * DIN;
    const __nv_bfloat16* Wl = g_wl + (size_t)(layer * 2 + dir) * G4 * DIN;

    float* bs = (float*)(smx + SMO_BIAS);
    if (tid < 128) bs[tid] = g_bias[(layer * 2 + dir) * G4 + nb + tid];

    {
        const int kc = 0;
#pragma unroll
        for (int j = 0; j < 8; j++) {
            int c = tid + j * 256;
            int arr = c >> 9, rem = c & 511, row = rem >> 2, ck = rem & 3;
            uint32_t dst = smb + SMO_TILES + arr * ARR_B + row * (LDS_T * 2) + ck * 16;
            const __nv_bfloat16* src;
            if (arr == 0)      src = Ah + (size_t)(mb + row) * DIN + kc + ck * 8;
            else if (arr == 1) src = Al + (size_t)(mb + row) * DIN + kc + ck * 8;
            else if (arr == 2) src = Wh + (size_t)(nb + row) * DIN + kc + ck * 8;
            else               src = Wl + (size_t)(nb + row) * DIN + kc + ck * 8;
            cpasync16(dst, src);
        }
        CP_COMMIT();
    }

    float acc[4][4][4];
#pragma unroll
    for (int mi = 0; mi < 4; mi++)
#pragma unroll
        for (int ni = 0; ni < 4; ni++)
#pragma unroll
            for (int q = 0; q < 4; q++) acc[mi][ni][q] = 0.f;

    for (int ch = 0; ch < DIN / KC; ch++) {
        if (ch + 1 < DIN / KC) {
            const int kc = (ch + 1) * KC;
            const uint32_t sb = smb + SMO_TILES + ((ch + 1) & 1) * STG_B;
#pragma unroll
            for (int j = 0; j < 8; j++) {
                int c = tid + j * 256;
                int arr = c >> 9, rem = c & 511, row = rem >> 2, ck = rem & 3;
                uint32_t dst = sb + arr * ARR_B + row * (LDS_T * 2) + ck * 16;
                const __nv_bfloat16* src;
                if (arr == 0)      src = Ah + (size_t)(mb + row) * DIN + kc + ck * 8;
                else if (arr == 1) src = Al + (size_t)(mb + row) * DIN + kc + ck * 8;
                else if (arr == 2) src = Wh + (size_t)(nb + row) * DIN + kc + ck * 8;
                else               src = Wl + (size_t)(nb + row) * DIN + kc + ck * 8;
                cpasync16(dst, src);
            }
            CP_COMMIT();
            CP_WAIT(1);
        } else {
            CP_WAIT(0);
        }
        __syncthreads();

        const uint32_t sA_h = smb + SMO_TILES + (ch & 1) * STG_B;
        const uint32_t sA_l = sA_h + ARR_B;
        const uint32_t sB_h = sA_h + 2 * ARR_B;
        const uint32_t sB_l = sA_h + 3 * ARR_B;

#pragma unroll
        for (int ks = 0; ks < 2; ks++) {
            const int k0 = ks * 16;
            const uint32_t aoff = ((lane & 15) * LDS_T + k0 + (lane >> 4) * 8) * 2;
            uint32_t ah[4][4], al[4][4];
#pragma unroll
            for (int mi = 0; mi < 4; mi++) {
                uint32_t ro = (wm * 64 + mi * 16) * (LDS_T * 2);
                ldm4(ah[mi], sA_h + ro + aoff);
                ldm4(al[mi], sA_l + ro + aoff);
            }
            uint32_t bh[2][4], bl[2][4];
#pragma unroll
            for (int nj = 0; nj < 2; nj++) {
                uint32_t ro = (wn * 32 + nj * 16) * (LDS_T * 2);
                ldm4(bh[nj], sB_h + ro + aoff);
                ldm4(bl[nj], sB_l + ro + aoff);
            }
#pragma unroll
            for (int mi = 0; mi < 4; mi++)
#pragma unroll
                for (int ni = 0; ni < 4; ni++) {
                    int nj = ni >> 1, hf = ni & 1;
                    mma_bf16(acc[mi][ni], ah[mi], bh[nj][hf], bh[nj][hf + 2]);
                    mma_bf16(acc[mi][ni], ah[mi], bl[nj][hf], bl[nj][hf + 2]);
                    mma_bf16(acc[mi][ni], al[mi], bh[nj][hf], bh[nj][hf + 2]);
                }
        }
        __syncthreads();
    }

    float* xp = g_xproj + (size_t)dir * TT * BB * G4;
    const int gid = lane >> 2, tig = lane & 3;
#pragma unroll
    for (int mi = 0; mi < 4; mi++) {
#pragma unroll
        for (int ni = 0; ni < 4; ni++) {
            int col = wn * 32 + ni * 8 + tig * 2;
            float b0 = bs[col], b1 = bs[col + 1];
            int r0 = mb + wm * 64 + mi * 16 + gid;
            float2 v0 = make_float2(acc[mi][ni][0] + b0, acc[mi][ni][1] + b1);
            float2 v1 = make_float2(acc[mi][ni][2] + b0, acc[mi][ni][3] + b1);
            *(float2*)(xp + (size_t)r0 * G4 + nb + col) = v0;
            *(float2*)(xp + (size_t)(r0 + 8) * G4 + nb + col) = v1;
        }
    }
}

// ---------------- recurrent persistent kernel (tensor-core) ------------------
// CTA: dir x 4 batch-groups (M=32) x 16 gate-slices (N=64).  K = 256.
#define RLDS  264                         // padded row stride (bf16 elems)
#define OW_H  0
#define OW_L  (OW_H + 64 * RLDS * 2)      // 33792
#define OH_H  (OW_L + 64 * RLDS * 2)      // 67584
#define OH_L  (OH_H + 32 * RLDS * 2)      // 84480
#define OS_S  (OH_L + 32 * RLDS * 2)      // 101376
#define SM_REC (OS_S + 32 * 68 * 4)       // 110080

__global__ void __launch_bounds__(128) k_lstm(
    const float* __restrict__ Whh, const int* __restrict__ lengths,
    float* __restrict__ dout, int layer)
{
    extern __shared__ char smx[];
    const uint32_t smb = smem_u32(smx);
    float* S = (float*)(smx + OS_S);      // [32][68] preacts

    const int bx  = blockIdx.x;
    const int dir = bx >> 6;
    const int cta = bx & 63;
    const int mg  = cta >> 4;             // batch group 0..3
    const int ns  = cta & 15;             // gate slice 0..15
    const int bb  = mg * 32;
    const int nbg = ns * 64;              // gate-col base
    const int ub  = ns * 16;              // unit base
    const int tid = threadIdx.x;
    const int lane = tid & 31;
    const int wn  = tid >> 5;             // warp = N16 slice
    const int gid = lane >> 2, tig = lane & 3;

    const float* W = Whh + (size_t)(layer * 2 + dir) * G4 * HH;

    // resident recurrent weights -> smem bf16 hi/lo (ldmatrix layout, once)
    for (int idx = tid; idx < 64 * 256; idx += 128) {
        int nl = idx >> 8; int k = idx & 255;
        int n = nbg + nl;
        int row = (n & 3) * HH + (n >> 2);
        float v = W[(size_t)row * HH + k];
        __nv_bfloat16 h, l;
        split_bf16(v, h, l);
        *(__nv_bfloat16*)(smx + OW_H + (nl * RLDS + k) * 2) = h;
        *(__nv_bfloat16*)(smx + OW_L + (nl * RLDS + k) * 2) = l;
    }

    // per-thread state: m = tid&31, units ug*4..ug*4+3
    const int m_loc = tid & 31;
    const int ug = tid >> 5;
    const int b_glob = bb + m_loc;
    const int u0 = ub + ug * 4;
    const int len = lengths[b_glob];

    float cs[4] = {0.f, 0.f, 0.f, 0.f};
    float hs[4] = {0.f, 0.f, 0.f, 0.f};

    // zero parity-0 h (this CTA's slice), reset flags
    *(uint4*)&g_hx[0][dir][b_glob][u0] = make_uint4(0, 0, 0, 0);
    if (tid == 0) g_flag[dir][mg][ns] = 0;

    gridbar();

    const float* xpbase = g_xproj + (size_t)dir * TT * BB * G4;

    // staging decomposition: 32 rows x 64 uint4
    const int sr = tid >> 2;              // row 0..31
    const int sq = tid & 3;               // quarter

    // prefetch first step's gates
    float4 pg[4];
    {
        int t0 = dir ? (TT - 1) : 0;
        const float4* src = (const float4*)(xpbase + ((size_t)t0 * BB + b_glob) * G4 + u0 * 4);
#pragma unroll
        for (int j = 0; j < 4; j++) pg[j] = src[j];
    }

    for (int s = 0; s < TT; s++) {
        int t = dir ? (TT - 1 - s) : s;
        int p = s & 1;

        // wait for our 16 producers (same dir, same batch group)
        if (tid < 16) {
            const unsigned* fp = &g_flag[dir][mg][tid];
            while (ld_acq(fp) < (unsigned)s) { }
        }
        __syncthreads();

        // stage h: packed global -> smem hi/lo bf16
        {
            const uint4* hsrc = (const uint4*)&g_hx[p][dir][bb + sr][0];
#pragma unroll
            for (int i = 0; i < 16; i++) {
                int idx = sq * 16 + i;
                uint4 v = __ldcg(hsrc + idx);
                uint32_t hiA = __byte_perm(v.x, v.y, 0x5410);
                uint32_t loA = __byte_perm(v.x, v.y, 0x7632);
                uint32_t hiB = __byte_perm(v.z, v.w, 0x5410);
                uint32_t loB = __byte_perm(v.z, v.w, 0x7632);
                uint32_t bo = (sr * RLDS + idx * 4) * 2;
                *(uint2*)(smx + OH_H + bo) = make_uint2(hiA, hiB);
                *(uint2*)(smx + OH_L + bo) = make_uint2(loA, loB);
            }
        }
        __syncthreads();

        // mma: S[32x64] = h @ Whh_slice^T (3-term bf16 split)
        float acc[2][2][4];
#pragma unroll
        for (int mi = 0; mi < 2; mi++)
#pragma unroll
            for (int ni = 0; ni < 2; ni++)
#pragma unroll
                for (int q = 0; q < 4; q++) acc[mi][ni][q] = 0.f;

        const uint32_t aoff = ((lane & 15) * RLDS + (lane >> 4) * 8) * 2;
        const uint32_t bbase = wn * 16 * RLDS * 2;
#pragma unroll 4
        for (int k0 = 0; k0 < HH; k0 += 16) {
            uint32_t koff = aoff + k0 * 2;
            uint32_t ah[2][4], al[2][4], bh[4], bl[4];
            ldm4(ah[0], smb + OH_H + koff);
            ldm4(ah[1], smb + OH_H + 16 * RLDS * 2 + koff);
            ldm4(al[0], smb + OH_L + koff);
            ldm4(al[1], smb + OH_L + 16 * RLDS * 2 + koff);
            ldm4(bh, smb + OW_H + bbase + koff);
            ldm4(bl, smb + OW_L + bbase + koff);
#pragma unroll
            for (int mi = 0; mi < 2; mi++)
#pragma unroll
                for (int ni = 0; ni < 2; ni++) {
                    mma_bf16(acc[mi][ni], ah[mi], bh[ni], bh[ni + 2]);
                    mma_bf16(acc[mi][ni], ah[mi], bl[ni], bl[ni + 2]);
                    mma_bf16(acc[mi][ni], al[mi], bh[ni], bh[ni + 2]);
                }
        }

        // accumulators -> smem S
#pragma unroll
        for (int mi = 0; mi < 2; mi++)
#pragma unroll
            for (int ni = 0; ni < 2; ni++) {
                int row = mi * 16 + gid;
                int col = wn * 16 + ni * 8 + tig * 2;
                *(float2*)&S[row * 68 + col] = make_float2(acc[mi][ni][0], acc[mi][ni][1]);
                *(float2*)&S[(row + 8) * 68 + col] = make_float2(acc[mi][ni][2], acc[mi][ni][3]);
            }
        __syncthreads();

        // pointwise: thread handles (m_loc, units u0..u0+3)
        const bool val = (t < len);
        uint32_t hpk[4];
        __nv_bfloat16 oh[4], ol[4];
        float of4[4];
#pragma unroll
        for (int j = 0; j < 4; j++) {
            float4 sg = *(const float4*)&S[m_loc * 68 + (ug * 4 + j) * 4];
            float4 g = pg[j];
            float gi = sigmfast(sg.x + g.x);
            float gf = sigmfast(sg.y + g.y);
            float gg = tanhfast(sg.z + g.z);
            float go = sigmfast(sg.w + g.w);
            float cn = gf * cs[j] + gi * gg;
            float hn = go * tanhfast(cn);
            if (val) { cs[j] = cn; hs[j] = hn; }
            float ov = val ? hn : 0.f;
            hpk[j] = pack_hl(hs[j]);
            split_bf16(ov, oh[j], ol[j]);
            of4[j] = ov;
        }
        *(uint4*)&g_hx[1 - p][dir][b_glob][u0] = make_uint4(hpk[0], hpk[1], hpk[2], hpk[3]);
        if (layer == 0) {
            size_t off = ((size_t)t * BB + b_glob) * DIN + dir * HH + u0;
            *(uint2*)(g_i2h + off) = *(uint2*)oh;
            *(uint2*)(g_i2l + off) = *(uint2*)ol;
        } else {
            *(float4*)(dout + ((size_t)b_glob * TT + t) * 512 + dir * HH + u0) = *(float4*)of4;
        }

        __syncthreads();                   // all h stores done (also protects S)
        if (tid == 0) {
            __threadfence();
            st_rel(&g_flag[dir][mg][ns], (unsigned)(s + 1));
        }

        // prefetch next step's gates (overlaps next flag wait)
        if (s + 1 < TT) {
            int t2 = dir ? (TT - 2 - s) : (s + 1);
            const float4* src = (const float4*)(xpbase + ((size_t)t2 * BB + b_glob) * G4 + u0 * 4);
#pragma unroll
            for (int j = 0; j < 4; j++) pg[j] = src[j];
        }
    }

    // final h_n / c_n (4 consecutive units -> float4)
    {
        size_t o = (size_t)((layer * 2 + dir) * BB + b_glob) * HH + u0;
        *(float4*)(dout + HN_OFF + o) = *(float4*)hs;
        *(float4*)(dout + CN_OFF + o) = *(float4*)cs;
    }
}

// ---------------- launch -----------------------------------------------------
extern "C" void kernel_launch(void* const* d_in, const int* in_sizes, int n_in,
                              void* d_out, int out_size)
{
    const float* x   = (const float*)d_in[0];
    const int*   len = (const int*)d_in[1];
    const float* Wih = (const float*)d_in[2];
    const float* Whh = (const float*)d_in[3];
    const float* bih = (const float*)d_in[4];
    const float* bhh = (const float*)d_in[5];
    float* out = (float*)d_out;

    cudaFuncSetAttribute(k_lstm, cudaFuncAttributeMaxDynamicSharedMemorySize, SM_REC);
    cudaFuncSetAttribute(k_gemm_tc, cudaFuncAttributeMaxDynamicSharedMemorySize, SM_GEMM);

    k_split_x<<<(MM * (DIN / 4) + 255) / 256, 256>>>(x);
    k_split_w<<<(4 * G4 * (DIN / 4) + 255) / 256, 256>>>(Wih, bih, bhh);

    k_gemm_tc<<<dim3(G4 / 128, MM / 128, 2), 256, SM_GEMM>>>(0);
    k_lstm<<<NBLK, 128, SM_REC>>>(Whh, len, out, 0);
    k_gemm_tc<<<dim3(G4 / 128, MM / 128, 2), 256, SM_GEMM>>>(1);
    k_lstm<<<NBLK, 128, SM_REC>>>(Whh, len, out, 1);
}

// round 6
// speedup vs baseline: 2.5179x; 1.3425x over previous
#include <cuda_runtime.h>
#include <cuda_fp16.h>
#include <cstdint>

#define BB   128      // batch
#define TT   512      // time
#define DIN  512      // input dim (also 2H for layer 1)
#define HH   256      // hidden
#define G4   1024     // 4*H
#define NBLK 128      // recurrent grid size
#define MM   (TT*BB)  // 65536 rows of A

#define HN_OFF 33554432ULL              // B*T*512
#define CN_OFF (HN_OFF + 131072ULL)     // + 4*B*H

// ---------------- device scratch (static, no runtime alloc) ----------------
__device__ __align__(256) __half g_xh[(size_t)MM * DIN];   // x hi (T,B,D)
__device__ __align__(256) __half g_xl[(size_t)MM * DIN];   // x lo
__device__ __align__(256) __half g_i2h[(size_t)MM * DIN];  // layer-1 input hi
__device__ __align__(256) __half g_i2l[(size_t)MM * DIN];  // layer-1 input lo
__device__ __align__(256) __half g_w[4ULL * G4 * DIN];     // permuted W_ih (fp16)
__device__ __align__(256) float g_bias[4 * G4];            // permuted b_ih+b_hh
__device__ __align__(256) float g_xproj[2ULL * TT * BB * G4];  // gate preacts
__device__ __align__(256) uint32_t g_hx[2][2][BB][HH];     // packed h (hi|lo<<16) fp16
__device__ unsigned g_flag[2][4][16];                      // dir, bgroup, nslice
__device__ unsigned long long g_bar = 0ULL;

// ---------------- small helpers --------------------------------------------
__device__ __forceinline__ float tanhfast(float x) {
    float y; asm("tanh.approx.f32 %0, %1;" : "=f"(y) : "f"(x)); return y;
}
__device__ __forceinline__ float sigmfast(float x) {
    return fmaf(0.5f, tanhfast(0.5f * x), 0.5f);
}
__device__ __forceinline__ unsigned ld_acq(const unsigned* p) {
    unsigned v; asm volatile("ld.acquire.gpu.u32 %0, [%1];" : "=r"(v) : "l"(p)); return v;
}
__device__ __forceinline__ void st_rel(unsigned* p, unsigned v) {
    asm volatile("st.release.gpu.u32 [%0], %1;" :: "l"(p), "r"(v));
}
__device__ __forceinline__ uint32_t smem_u32(const void* p) {
    uint32_t a;
    asm("{ .reg .u64 t; cvta.to.shared.u64 t, %1; cvt.u32.u64 %0, t; }" : "=r"(a) : "l"(p));
    return a;
}
__device__ __forceinline__ void split_f16(float v, __half& h, __half& l) {
    h = __float2half_rn(v);
    l = __float2half_rn(v - __half2float(h));
}
__device__ __forceinline__ uint32_t pack_hl(float v) {
    __half h, l;
    split_f16(v, h, l);
    return (uint32_t)__half_as_ushort(h) | ((uint32_t)__half_as_ushort(l) << 16);
}

// ---------------- mma.sync / ldmatrix / cp.async wrappers -------------------
__device__ __forceinline__ void ldm4(uint32_t* r, uint32_t addr) {
    asm volatile("ldmatrix.sync.aligned.m8n8.x4.shared.b16 {%0,%1,%2,%3}, [%4];"
                 : "=r"(r[0]), "=r"(r[1]), "=r"(r[2]), "=r"(r[3]) : "r"(addr));
}
__device__ __forceinline__ void mma_f16(float* d, const uint32_t* a,
                                        uint32_t b0, uint32_t b1) {
    asm volatile(
        "mma.sync.aligned.m16n8k16.row.col.f32.f16.f16.f32 "
        "{%0,%1,%2,%3}, {%4,%5,%6,%7}, {%8,%9}, {%0,%1,%2,%3};"
        : "+f"(d[0]), "+f"(d[1]), "+f"(d[2]), "+f"(d[3])
        : "r"(a[0]), "r"(a[1]), "r"(a[2]), "r"(a[3]), "r"(b0), "r"(b1));
}
__device__ __forceinline__ void cpasync16(uint32_t dst, const void* src) {
    asm volatile("cp.async.cg.shared.global [%0], [%1], 16;" :: "r"(dst), "l"(src));
}
#define CP_COMMIT() asm volatile("cp.async.commit_group;" ::: "memory")
#define CP_WAIT(n)  asm volatile("cp.async.wait_group %0;" :: "n"(n) : "memory")

// ---------------- global barrier (monotonic, once per lstm launch) ----------
__device__ __forceinline__ void gridbar()
{
    __syncthreads();
    if (threadIdx.x == 0) {
        __threadfence();
        unsigned long long t = atomicAdd(&g_bar, 1ULL) + 1ULL;
        unsigned long long target = ((t + NBLK - 1ULL) / NBLK) * NBLK;
        while (atomicAdd(&g_bar, 0ULL) < target) { __nanosleep(64); }
        __threadfence();
    }
    __syncthreads();
}

// ---------------- split + transpose x: (B,T,D) fp32 -> (T,B,D) fp16 hi/lo ---
__global__ void k_split_x(const float* __restrict__ x)
{
    int i = blockIdx.x * blockDim.x + threadIdx.x;       // float4 index
    const int N4 = MM * (DIN / 4);
    if (i >= N4) return;
    int k4 = i & 127;
    int bt = i >> 7;
    int t = bt & (TT - 1);
    int b = bt >> 9;
    float4 v = ((const float4*)x)[i];
    __half h[4], l[4];
    split_f16(v.x, h[0], l[0]); split_f16(v.y, h[1], l[1]);
    split_f16(v.z, h[2], l[2]); split_f16(v.w, h[3], l[3]);
    size_t off = ((size_t)t * BB + b) * DIN + k4 * 4;
    *(uint2*)(g_xh + off) = *(uint2*)h;
    *(uint2*)(g_xl + off) = *(uint2*)l;
}

// ---------------- convert + permute weights (fp16 single) -------------------
__global__ void k_split_w(const float* __restrict__ Wih, const float* __restrict__ bih,
                          const float* __restrict__ bhh)
{
    int i = blockIdx.x * blockDim.x + threadIdx.x;       // (ld, n, k4)
    if (i >= 4 * G4 * (DIN / 4)) return;
    int k4 = i & 127;
    int rest = i >> 7;
    int n = rest & (G4 - 1);
    int ld = rest >> 10;
    int r = (n & 3) * HH + (n >> 2);
    float4 v = *(const float4*)(Wih + ((size_t)ld * G4 + r) * DIN + k4 * 4);
    __half h[4];
    h[0] = __float2half_rn(v.x); h[1] = __float2half_rn(v.y);
    h[2] = __float2half_rn(v.z); h[3] = __float2half_rn(v.w);
    size_t off = ((size_t)ld * G4 + n) * DIN + k4 * 4;
    *(uint2*)(g_w + off) = *(uint2*)h;
    if (k4 == 0)
        g_bias[ld * G4 + n] = bih[ld * G4 + r] + bhh[ld * G4 + r];
}

// ---------------- mma.sync input-projection GEMM (2-term fp16) ---------------
#define KC     32
#define LDS_T  40
#define ARR_B  (128 * LDS_T * 2)           // 10240
#define STG_B  (3 * ARR_B)                 // 30720
#define SMO_BIAS  0
#define SMO_TILES 512
#define SM_GEMM   (SMO_TILES + 2 * STG_B)  // 61952

__global__ void __launch_bounds__(256, 2) k_gemm_tc(int layer)
{
    extern __shared__ char smx[];
    const uint32_t smb = smem_u32(smx);
    const int tid = threadIdx.x;
    const int lane = tid & 31;
    const int w   = tid >> 5;
    const int wm  = w & 1;
    const int wn  = w >> 1;
    const int dir = blockIdx.z;
    const int mb  = blockIdx.y * 128;
    const int nb  = blockIdx.x * 128;

    const __half* Ah = layer ? g_i2h : g_xh;
    const __half* Al = layer ? g_i2l : g_xl;
    const __half* Wd = g_w + (size_t)(layer * 2 + dir) * G4 * DIN;

    float* bs = (float*)(smx + SMO_BIAS);
    if (tid < 128) bs[tid] = g_bias[(layer * 2 + dir) * G4 + nb + tid];

    // stage copy: 3 arrays x 128 rows x 4 chunks = 1536 cps, 6 per thread
    {
        const int kc = 0;
#pragma unroll
        for (int j = 0; j < 6; j++) {
            int c = tid + j * 256;
            int arr = c >> 9, rem = c & 511, row = rem >> 2, ck = rem & 3;
            uint32_t dst = smb + SMO_TILES + arr * ARR_B + row * (LDS_T * 2) + ck * 16;
            const __half* src;
            if (arr == 0)      src = Ah + (size_t)(mb + row) * DIN + kc + ck * 8;
            else if (arr == 1) src = Al + (size_t)(mb + row) * DIN + kc + ck * 8;
            else               src = Wd + (size_t)(nb + row) * DIN + kc + ck * 8;
            cpasync16(dst, src);
        }
        CP_COMMIT();
    }

    float acc[4][4][4];
#pragma unroll
    for (int mi = 0; mi < 4; mi++)
#pragma unroll
        for (int ni = 0; ni < 4; ni++)
#pragma unroll
            for (int q = 0; q < 4; q++) acc[mi][ni][q] = 0.f;

    for (int ch = 0; ch < DIN / KC; ch++) {
        if (ch + 1 < DIN / KC) {
            const int kc = (ch + 1) * KC;
            const uint32_t sb = smb + SMO_TILES + ((ch + 1) & 1) * STG_B;
#pragma unroll
            for (int j = 0; j < 6; j++) {
                int c = tid + j * 256;
                int arr = c >> 9, rem = c & 511, row = rem >> 2, ck = rem & 3;
                uint32_t dst = sb + arr * ARR_B + row * (LDS_T * 2) + ck * 16;
                const __half* src;
                if (arr == 0)      src = Ah + (size_t)(mb + row) * DIN + kc + ck * 8;
                else if (arr == 1) src = Al + (size_t)(mb + row) * DIN + kc + ck * 8;
                else               src = Wd + (size_t)(nb + row) * DIN + kc + ck * 8;
                cpasync16(dst, src);
            }
            CP_COMMIT();
            CP_WAIT(1);
        } else {
            CP_WAIT(0);
        }
        __syncthreads();

        const uint32_t sA_h = smb + SMO_TILES + (ch & 1) * STG_B;
        const uint32_t sA_l = sA_h + ARR_B;
        const uint32_t sB   = sA_h + 2 * ARR_B;

#pragma unroll
        for (int ks = 0; ks < 2; ks++) {
            const int k0 = ks * 16;
            const uint32_t aoff = ((lane & 15) * LDS_T + k0 + (lane >> 4) * 8) * 2;
            uint32_t ah[4][4], al[4][4];
#pragma unroll
            for (int mi = 0; mi < 4; mi++) {
                uint32_t ro = (wm * 64 + mi * 16) * (LDS_T * 2);
                ldm4(ah[mi], sA_h + ro + aoff);
                ldm4(al[mi], sA_l + ro + aoff);
            }
            uint32_t bh[2][4];
#pragma unroll
            for (int nj = 0; nj < 2; nj++) {
                uint32_t ro = (wn * 32 + nj * 16) * (LDS_T * 2);
                ldm4(bh[nj], sB + ro + aoff);
            }
#pragma unroll
            for (int mi = 0; mi < 4; mi++)
#pragma unroll
                for (int ni = 0; ni < 4; ni++) {
                    int nj = ni >> 1, hf = ni & 1;
                    mma_f16(acc[mi][ni], ah[mi], bh[nj][hf], bh[nj][hf + 2]);
                    mma_f16(acc[mi][ni], al[mi], bh[nj][hf], bh[nj][hf + 2]);
                }
        }
        __syncthreads();
    }

    float* xp = g_xproj + (size_t)dir * TT * BB * G4;
    const int gid = lane >> 2, tig = lane & 3;
#pragma unroll
    for (int mi = 0; mi < 4; mi++) {
#pragma unroll
        for (int ni = 0; ni < 4; ni++) {
            int col = wn * 32 + ni * 8 + tig * 2;
            float b0 = bs[col], b1 = bs[col + 1];
            int r0 = mb + wm * 64 + mi * 16 + gid;
            float2 v0 = make_float2(acc[mi][ni][0] + b0, acc[mi][ni][1] + b1);
            float2 v1 = make_float2(acc[mi][ni][2] + b0, acc[mi][ni][3] + b1);
            *(float2*)(xp + (size_t)r0 * G4 + nb + col) = v0;
            *(float2*)(xp + (size_t)(r0 + 8) * G4 + nb + col) = v1;
        }
    }
}

// ---------------- recurrent persistent kernel (tensor-core, 2-term) ----------
// CTA: dir x 4 batch-groups (M=32) x 16 gate-slices (N=64).  K = 256.
#define RLDS  264                         // padded row stride (fp16 elems)
#define OW_S  0
#define OH_H  (OW_S + 64 * RLDS * 2)      // 33792
#define OH_L  (OH_H + 32 * RLDS * 2)      // 50688
#define OS_S  (OH_L + 32 * RLDS * 2)      // 67584
#define SM_REC (OS_S + 32 * 68 * 4)       // 76288

__global__ void __launch_bounds__(128) k_lstm(
    const float* __restrict__ Whh, const int* __restrict__ lengths,
    float* __restrict__ dout, int layer)
{
    extern __shared__ char smx[];
    const uint32_t smb = smem_u32(smx);
    float* S = (float*)(smx + OS_S);      // [32][68] preacts

    const int bx  = blockIdx.x;
    const int dir = bx >> 6;
    const int cta = bx & 63;
    const int mg  = cta >> 4;             // batch group 0..3
    const int ns  = cta & 15;             // gate slice 0..15
    const int bb  = mg * 32;
    const int nbg = ns * 64;              // gate-col base
    const int ub  = ns * 16;              // unit base
    const int tid = threadIdx.x;
    const int lane = tid & 31;
    const int wn  = tid >> 5;             // warp = N16 slice
    const int gid = lane >> 2, tig = lane & 3;

    const float* W = Whh + (size_t)(layer * 2 + dir) * G4 * HH;

    // resident recurrent weights -> smem fp16 (ldmatrix layout, once)
    for (int idx = tid; idx < 64 * 256; idx += 128) {
        int nl = idx >> 8; int k = idx & 255;
        int n = nbg + nl;
        int row = (n & 3) * HH + (n >> 2);
        *(__half*)(smx + OW_S + (nl * RLDS + k) * 2) = __float2half_rn(W[(size_t)row * HH + k]);
    }

    // per-thread state: m = tid&31, units ug*4..ug*4+3
    const int m_loc = tid & 31;
    const int ug = tid >> 5;
    const int b_glob = bb + m_loc;
    const int u0 = ub + ug * 4;
    const int len = lengths[b_glob];

    float cs[4] = {0.f, 0.f, 0.f, 0.f};
    float hs[4] = {0.f, 0.f, 0.f, 0.f};

    // zero parity-0 h (this CTA's slice), reset flags
    *(uint4*)&g_hx[0][dir][b_glob][u0] = make_uint4(0, 0, 0, 0);
    if (tid == 0) g_flag[dir][mg][ns] = 0;

    gridbar();

    const float* xpbase = g_xproj + (size_t)dir * TT * BB * G4;

    const int sr = tid >> 2;              // staging row 0..31
    const int sq = tid & 3;               // quarter

    float4 pg[4];
    {
        int t0 = dir ? (TT - 1) : 0;
        const float4* src = (const float4*)(xpbase + ((size_t)t0 * BB + b_glob) * G4 + u0 * 4);
#pragma unroll
        for (int j = 0; j < 4; j++) pg[j] = src[j];
    }

    for (int s = 0; s < TT; s++) {
        int t = dir ? (TT - 1 - s) : s;
        int p = s & 1;

        // wait for our 16 producers (same dir, same batch group)
        if (tid < 16) {
            const unsigned* fp = &g_flag[dir][mg][tid];
            while (ld_acq(fp) < (unsigned)s) { }
        }
        __syncthreads();

        // stage h: packed global -> smem hi/lo fp16
        {
            const uint4* hsrc = (const uint4*)&g_hx[p][dir][bb + sr][0];
#pragma unroll
            for (int i = 0; i < 16; i++) {
                int idx = sq * 16 + i;
                uint4 v = __ldcg(hsrc + idx);
                uint32_t hiA = __byte_perm(v.x, v.y, 0x5410);
                uint32_t loA = __byte_perm(v.x, v.y, 0x7632);
                uint32_t hiB = __byte_perm(v.z, v.w, 0x5410);
                uint32_t loB = __byte_perm(v.z, v.w, 0x7632);
                uint32_t bo = (sr * RLDS + idx * 4) * 2;
                *(uint2*)(smx + OH_H + bo) = make_uint2(hiA, hiB);
                *(uint2*)(smx + OH_L + bo) = make_uint2(loA, loB);
            }
        }
        __syncthreads();

        // mma: S[32x64] = h @ Whh_slice^T (2-term fp16 split)
        float acc[2][2][4];
#pragma unroll
        for (int mi = 0; mi < 2; mi++)
#pragma unroll
            for (int ni = 0; ni < 2; ni++)
#pragma unroll
                for (int q = 0; q < 4; q++) acc[mi][ni][q] = 0.f;

        const uint32_t aoff = ((lane & 15) * RLDS + (lane >> 4) * 8) * 2;
        const uint32_t bbase = wn * 16 * RLDS * 2;
#pragma unroll 4
        for (int k0 = 0; k0 < HH; k0 += 16) {
            uint32_t koff = aoff + k0 * 2;
            uint32_t ah[2][4], al[2][4], bh[4];
            ldm4(ah[0], smb + OH_H + koff);
            ldm4(ah[1], smb + OH_H + 16 * RLDS * 2 + koff);
            ldm4(al[0], smb + OH_L + koff);
            ldm4(al[1], smb + OH_L + 16 * RLDS * 2 + koff);
            ldm4(bh, smb + OW_S + bbase + koff);
#pragma unroll
            for (int mi = 0; mi < 2; mi++)
#pragma unroll
                for (int ni = 0; ni < 2; ni++) {
                    mma_f16(acc[mi][ni], ah[mi], bh[ni], bh[ni + 2]);
                    mma_f16(acc[mi][ni], al[mi], bh[ni], bh[ni + 2]);
                }
        }

        // accumulators -> smem S
#pragma unroll
        for (int mi = 0; mi < 2; mi++)
#pragma unroll
            for (int ni = 0; ni < 2; ni++) {
                int row = mi * 16 + gid;
                int col = wn * 16 + ni * 8 + tig * 2;
                *(float2*)&S[row * 68 + col] = make_float2(acc[mi][ni][0], acc[mi][ni][1]);
                *(float2*)&S[(row + 8) * 68 + col] = make_float2(acc[mi][ni][2], acc[mi][ni][3]);
            }
        __syncthreads();

        // pointwise: thread handles (m_loc, units u0..u0+3)
        const bool val = (t < len);
        uint32_t hpk[4];
        __half oh[4], ol[4];
        float of4[4];
#pragma unroll
        for (int j = 0; j < 4; j++) {
            float4 sg = *(const float4*)&S[m_loc * 68 + (ug * 4 + j) * 4];
            float4 g = pg[j];
            float gi = sigmfast(sg.x + g.x);
            float gf = sigmfast(sg.y + g.y);
            float gg = tanhfast(sg.z + g.z);
            float go = sigmfast(sg.w + g.w);
            float cn = gf * cs[j] + gi * gg;
            float hn = go * tanhfast(cn);
            if (val) { cs[j] = cn; hs[j] = hn; }
            float ov = val ? hn : 0.f;
            hpk[j] = pack_hl(hs[j]);
            split_f16(ov, oh[j], ol[j]);
            of4[j] = ov;
        }
        // critical path first: publish h, then flag
        *(uint4*)&g_hx[1 - p][dir][b_glob][u0] = make_uint4(hpk[0], hpk[1], hpk[2], hpk[3]);
        __syncthreads();                   // all h stores done (also protects S)
        if (tid == 0)
            st_rel(&g_flag[dir][mg][ns], (unsigned)(s + 1));  // release orders h stores

        // off critical path: outputs + prefetch
        if (layer == 0) {
            size_t off = ((size_t)t * BB + b_glob) * DIN + dir * HH + u0;
            *(uint2*)(g_i2h + off) = *(uint2*)oh;
            *(uint2*)(g_i2l + off) = *(uint2*)ol;
        } else {
            *(float4*)(dout + ((size_t)b_glob * TT + t) * 512 + dir * HH + u0) = *(float4*)of4;
        }
        if (s + 1 < TT) {
            int t2 = dir ? (TT - 2 - s) : (s + 1);
            const float4* src = (const float4*)(xpbase + ((size_t)t2 * BB + b_glob) * G4 + u0 * 4);
#pragma unroll
            for (int j = 0; j < 4; j++) pg[j] = src[j];
        }
    }

    // final h_n / c_n (4 consecutive units -> float4)
    {
        size_t o = (size_t)((layer * 2 + dir) * BB + b_glob) * HH + u0;
        *(float4*)(dout + HN_OFF + o) = *(float4*)hs;
        *(float4*)(dout + CN_OFF + o) = *(float4*)cs;
    }
}

// ---------------- launch -----------------------------------------------------
extern "C" void kernel_launch(void* const* d_in, const int* in_sizes, int n_in,
                              void* d_out, int out_size)
{
    const float* x   = (const float*)d_in[0];
    const int*   len = (const int*)d_in[1];
    const float* Wih = (const float*)d_in[2];
    const float* Whh = (const float*)d_in[3];
    const float* bih = (const float*)d_in[4];
    const float* bhh = (const float*)d_in[5];
    float* out = (float*)d_out;

    cudaFuncSetAttribute(k_lstm, cudaFuncAttributeMaxDynamicSharedMemorySize, SM_REC);
    cudaFuncSetAttribute(k_gemm_tc, cudaFuncAttributeMaxDynamicSharedMemorySize, SM_GEMM);

    k_split_x<<<(MM * (DIN / 4) + 255) / 256, 256>>>(x);
    k_split_w<<<(4 * G4 * (DIN / 4) + 255) / 256, 256>>>(Wih, bih, bhh);

    k_gemm_tc<<<dim3(G4 / 128, MM / 128, 2), 256, SM_GEMM>>>(0);
    k_lstm<<<NBLK, 128, SM_REC>>>(Whh, len, out, 0);
    k_gemm_tc<<<dim3(G4 / 128, MM / 128, 2), 256, SM_GEMM>>>(1);
    k_lstm<<<NBLK, 128, SM_REC>>>(Whh, len, out, 1);
}

// round 7
// speedup vs baseline: 2.6195x; 1.0404x over previous
#include <cuda_runtime.h>
#include <cuda_fp16.h>
#include <cstdint>

#define BB   128      // batch
#define TT   512      // time
#define DIN  512      // input dim (also 2H for layer 1)
#define HH   256      // hidden
#define G4   1024     // 4*H
#define MM   (TT*BB)  // 65536 rows of A

#define HN_OFF 33554432ULL              // B*T*512
#define CN_OFF (HN_OFF + 131072ULL)     // + 4*B*H

// ---------------- device scratch (static, no runtime alloc) ----------------
__device__ __align__(256) __half g_xh[(size_t)MM * DIN];   // x hi (T,B,D)
__device__ __align__(256) __half g_xl[(size_t)MM * DIN];   // x lo
__device__ __align__(256) __half g_i2h[(size_t)MM * DIN];  // layer-1 input hi
__device__ __align__(256) __half g_i2l[(size_t)MM * DIN];  // layer-1 input lo
__device__ __align__(256) __half g_w[4ULL * G4 * DIN];     // permuted W_ih (fp16)
__device__ __align__(256) float g_bias[4 * G4];            // permuted b_ih+b_hh
__device__ __align__(256) float g_xproj[2ULL * TT * BB * G4];  // gate preacts

// ---------------- small helpers --------------------------------------------
__device__ __forceinline__ float tanhfast(float x) {
    float y; asm("tanh.approx.f32 %0, %1;" : "=f"(y) : "f"(x)); return y;
}
__device__ __forceinline__ float sigmfast(float x) {
    return fmaf(0.5f, tanhfast(0.5f * x), 0.5f);
}
__device__ __forceinline__ uint32_t smem_u32(const void* p) {
    uint32_t a;
    asm("{ .reg .u64 t; cvta.to.shared.u64 t, %1; cvt.u32.u64 %0, t; }" : "=r"(a) : "l"(p));
    return a;
}
__device__ __forceinline__ void split_f16(float v, __half& h, __half& l) {
    h = __float2half_rn(v);
    l = __float2half_rn(v - __half2float(h));
}

// ---------------- mma.sync / ldmatrix / cp.async / cluster wrappers ---------
__device__ __forceinline__ void ldm4(uint32_t* r, uint32_t addr) {
    asm volatile("ldmatrix.sync.aligned.m8n8.x4.shared.b16 {%0,%1,%2,%3}, [%4];"
                 : "=r"(r[0]), "=r"(r[1]), "=r"(r[2]), "=r"(r[3]) : "r"(addr));
}
__device__ __forceinline__ void mma_f16(float* d, const uint32_t* a,
                                        uint32_t b0, uint32_t b1) {
    asm volatile(
        "mma.sync.aligned.m16n8k16.row.col.f32.f16.f16.f32 "
        "{%0,%1,%2,%3}, {%4,%5,%6,%7}, {%8,%9}, {%0,%1,%2,%3};"
        : "+f"(d[0]), "+f"(d[1]), "+f"(d[2]), "+f"(d[3])
        : "r"(a[0]), "r"(a[1]), "r"(a[2]), "r"(a[3]), "r"(b0), "r"(b1));
}
__device__ __forceinline__ void cpasync16(uint32_t dst, const void* src) {
    asm volatile("cp.async.cg.shared.global [%0], [%1], 16;" :: "r"(dst), "l"(src));
}
#define CP_COMMIT() asm volatile("cp.async.commit_group;" ::: "memory")
#define CP_WAIT(n)  asm volatile("cp.async.wait_group %0;" :: "n"(n) : "memory")
#define CLUSTER_SYNC() do { \
    asm volatile("barrier.cluster.arrive.aligned;" ::: "memory"); \
    asm volatile("barrier.cluster.wait.aligned;" ::: "memory"); \
} while (0)
__device__ __forceinline__ uint32_t mapa_u32(uint32_t laddr, uint32_t rank) {
    uint32_t r;
    asm volatile("mapa.shared::cluster.u32 %0, %1, %2;" : "=r"(r) : "r"(laddr), "r"(rank));
    return r;
}
__device__ __forceinline__ void st_clu(uint32_t addr, uint32_t v) {
    asm volatile("st.shared::cluster.u32 [%0], %1;" :: "r"(addr), "r"(v));
}

// ---------------- split + transpose x: (B,T,D) fp32 -> (T,B,D) fp16 hi/lo ---
__global__ void k_split_x(const float* __restrict__ x)
{
    int i = blockIdx.x * blockDim.x + threadIdx.x;       // float4 index
    const int N4 = MM * (DIN / 4);
    if (i >= N4) return;
    int k4 = i & 127;
    int bt = i >> 7;
    int t = bt & (TT - 1);
    int b = bt >> 9;
    float4 v = ((const float4*)x)[i];
    __half h[4], l[4];
    split_f16(v.x, h[0], l[0]); split_f16(v.y, h[1], l[1]);
    split_f16(v.z, h[2], l[2]); split_f16(v.w, h[3], l[3]);
    size_t off = ((size_t)t * BB + b) * DIN + k4 * 4;
    *(uint2*)(g_xh + off) = *(uint2*)h;
    *(uint2*)(g_xl + off) = *(uint2*)l;
}

// ---------------- convert + permute weights (fp16 single) -------------------
__global__ void k_split_w(const float* __restrict__ Wih, const float* __restrict__ bih,
                          const float* __restrict__ bhh)
{
    int i = blockIdx.x * blockDim.x + threadIdx.x;       // (ld, n, k4)
    if (i >= 4 * G4 * (DIN / 4)) return;
    int k4 = i & 127;
    int rest = i >> 7;
    int n = rest & (G4 - 1);
    int ld = rest >> 10;
    int r = (n & 3) * HH + (n >> 2);
    float4 v = *(const float4*)(Wih + ((size_t)ld * G4 + r) * DIN + k4 * 4);
    __half h[4];
    h[0] = __float2half_rn(v.x); h[1] = __float2half_rn(v.y);
    h[2] = __float2half_rn(v.z); h[3] = __float2half_rn(v.w);
    size_t off = ((size_t)ld * G4 + n) * DIN + k4 * 4;
    *(uint2*)(g_w + off) = *(uint2*)h;
    if (k4 == 0)
        g_bias[ld * G4 + n] = bih[ld * G4 + r] + bhh[ld * G4 + r];
}

// ---------------- mma.sync input-projection GEMM (2-term fp16) ---------------
#define KC     32
#define LDS_T  40
#define ARR_B  (128 * LDS_T * 2)           // 10240
#define STG_B  (3 * ARR_B)                 // 30720
#define SMO_BIAS  0
#define SMO_TILES 512
#define SM_GEMM   (SMO_TILES + 2 * STG_B)  // 61952

__global__ void __launch_bounds__(256, 2) k_gemm_tc(int layer)
{
    extern __shared__ char smx[];
    const uint32_t smb = smem_u32(smx);
    const int tid = threadIdx.x;
    const int lane = tid & 31;
    const int w   = tid >> 5;
    const int wm  = w & 1;
    const int wn  = w >> 1;
    const int dir = blockIdx.z;
    const int mb  = blockIdx.y * 128;
    const int nb  = blockIdx.x * 128;

    const __half* Ah = layer ? g_i2h : g_xh;
    const __half* Al = layer ? g_i2l : g_xl;
    const __half* Wd = g_w + (size_t)(layer * 2 + dir) * G4 * DIN;

    float* bs = (float*)(smx + SMO_BIAS);
    if (tid < 128) bs[tid] = g_bias[(layer * 2 + dir) * G4 + nb + tid];

    {
        const int kc = 0;
#pragma unroll
        for (int j = 0; j < 6; j++) {
            int c = tid + j * 256;
            int arr = c >> 9, rem = c & 511, row = rem >> 2, ck = rem & 3;
            uint32_t dst = smb + SMO_TILES + arr * ARR_B + row * (LDS_T * 2) + ck * 16;
            const __half* src;
            if (arr == 0)      src = Ah + (size_t)(mb + row) * DIN + kc + ck * 8;
            else if (arr == 1) src = Al + (size_t)(mb + row) * DIN + kc + ck * 8;
            else               src = Wd + (size_t)(nb + row) * DIN + kc + ck * 8;
            cpasync16(dst, src);
        }
        CP_COMMIT();
    }

    float acc[4][4][4];
#pragma unroll
    for (int mi = 0; mi < 4; mi++)
#pragma unroll
        for (int ni = 0; ni < 4; ni++)
#pragma unroll
            for (int q = 0; q < 4; q++) acc[mi][ni][q] = 0.f;

    for (int ch = 0; ch < DIN / KC; ch++) {
        if (ch + 1 < DIN / KC) {
            const int kc = (ch + 1) * KC;
            const uint32_t sb = smb + SMO_TILES + ((ch + 1) & 1) * STG_B;
#pragma unroll
            for (int j = 0; j < 6; j++) {
                int c = tid + j * 256;
                int arr = c >> 9, rem = c & 511, row = rem >> 2, ck = rem & 3;
                uint32_t dst = sb + arr * ARR_B + row * (LDS_T * 2) + ck * 16;
                const __half* src;
                if (arr == 0)      src = Ah + (size_t)(mb + row) * DIN + kc + ck * 8;
                else if (arr == 1) src = Al + (size_t)(mb + row) * DIN + kc + ck * 8;
                else               src = Wd + (size_t)(nb + row) * DIN + kc + ck * 8;
                cpasync16(dst, src);
            }
            CP_COMMIT();
            CP_WAIT(1);
        } else {
            CP_WAIT(0);
        }
        __syncthreads();

        const uint32_t sA_h = smb + SMO_TILES + (ch & 1) * STG_B;
        const uint32_t sA_l = sA_h + ARR_B;
        const uint32_t sB   = sA_h + 2 * ARR_B;

#pragma unroll
        for (int ks = 0; ks < 2; ks++) {
            const int k0 = ks * 16;
            const uint32_t aoff = ((lane & 15) * LDS_T + k0 + (lane >> 4) * 8) * 2;
            uint32_t ah[4][4], al[4][4];
#pragma unroll
            for (int mi = 0; mi < 4; mi++) {
                uint32_t ro = (wm * 64 + mi * 16) * (LDS_T * 2);
                ldm4(ah[mi], sA_h + ro + aoff);
                ldm4(al[mi], sA_l + ro + aoff);
            }
            uint32_t bh[2][4];
#pragma unroll
            for (int nj = 0; nj < 2; nj++) {
                uint32_t ro = (wn * 32 + nj * 16) * (LDS_T * 2);
                ldm4(bh[nj], sB + ro + aoff);
            }
#pragma unroll
            for (int mi = 0; mi < 4; mi++)
#pragma unroll
                for (int ni = 0; ni < 4; ni++) {
                    int nj = ni >> 1, hf = ni & 1;
                    mma_f16(acc[mi][ni], ah[mi], bh[nj][hf], bh[nj][hf + 2]);
                    mma_f16(acc[mi][ni], al[mi], bh[nj][hf], bh[nj][hf + 2]);
                }
        }
        __syncthreads();
    }

    float* xp = g_xproj + (size_t)dir * TT * BB * G4;
    const int gid = lane >> 2, tig = lane & 3;
#pragma unroll
    for (int mi = 0; mi < 4; mi++) {
#pragma unroll
        for (int ni = 0; ni < 4; ni++) {
            int col = wn * 32 + ni * 8 + tig * 2;
            float b0 = bs[col], b1 = bs[col + 1];
            int r0 = mb + wm * 64 + mi * 16 + gid;
            float2 v0 = make_float2(acc[mi][ni][0] + b0, acc[mi][ni][1] + b1);
            float2 v1 = make_float2(acc[mi][ni][2] + b0, acc[mi][ni][3] + b1);
            *(float2*)(xp + (size_t)r0 * G4 + nb + col) = v0;
            *(float2*)(xp + (size_t)(r0 + 8) * G4 + nb + col) = v1;
        }
    }
}

// ---------------- recurrent persistent kernel (cluster + DSMEM) --------------
// grid = 2 dir x 8 bgroup (M=16) x 8 nslice (N=128).  Cluster = the 8 nslices.
#define RLDS  264                          // padded row stride (fp16 elems)
#define OW_S  0                            // W slice: 128 x 256 fp16
#define AB_SZ (16 * RLDS * 2)              // 8448 per A array
#define OA_H0 (OW_S + 128 * RLDS * 2)      // 67584
#define OA_L0 (OA_H0 + AB_SZ)              // 76032
#define OA_H1 (OA_L0 + AB_SZ)              // 84480
#define OA_L1 (OA_H1 + AB_SZ)              // 92928
#define OS_S  (OA_L1 + AB_SZ)              // 101376  S: 16 x 132 f32
#define SM_REC (OS_S + 16 * 132 * 4)       // 109824

__global__ void __launch_bounds__(256) __cluster_dims__(8, 1, 1)
k_lstm(const float* __restrict__ Whh, const int* __restrict__ lengths,
       float* __restrict__ dout, int layer)
{
    extern __shared__ char smx[];
    const uint32_t smb = smem_u32(smx);
    float* S = (float*)(smx + OS_S);

    const int cid = blockIdx.x >> 3;      // cluster id 0..15
    const int dir = cid >> 3;             // 0..1
    const int mg  = cid & 7;              // batch group 0..7 (M=16)
    const int ns  = blockIdx.x & 7;       // n-slice (== cluster ctarank)
    const int tid = threadIdx.x;
    const int lane = tid & 31;
    const int wn  = tid >> 5;             // warp 0..7 -> 16 gate cols each
    const int gid = lane >> 2, tig = lane & 3;

    const float* W = Whh + (size_t)(layer * 2 + dir) * G4 * HH;

    // resident W_hh slice (128 gate cols x 256) -> smem fp16, once
    for (int idx = tid; idx < 128 * 256; idx += 256) {
        int nl = idx >> 8; int k = idx & 255;
        int n = ns * 128 + nl;
        int row = (n & 3) * HH + (n >> 2);
        *(__half*)(smx + OW_S + (nl * RLDS + k) * 2) = __float2half_rn(W[(size_t)row * HH + k]);
    }
    // zero both parities of A (hi+lo): 4 arrays x 8448 B
    for (int idx = tid; idx < 4 * AB_SZ / 4; idx += 256)
        *(uint32_t*)(smx + OA_H0 + idx * 4) = 0;

    // per-thread pointwise mapping: batch m = tid&15, 2 units
    const int m_loc = tid & 15;
    const int ug = tid >> 4;              // 0..15
    const int b_glob = mg * 16 + m_loc;
    const int u0g = ns * 32 + ug * 2;     // global unit index (col in A)
    const int len = lengths[b_glob];

    float cs[2] = {0.f, 0.f};
    float hs[2] = {0.f, 0.f};

    const float* xpbase = g_xproj + (size_t)dir * TT * BB * G4;

    // prefetch first step's gates (2 units x 4 gates)
    float4 pg[2];
    {
        int t0 = dir ? (TT - 1) : 0;
        const float4* src = (const float4*)(xpbase + ((size_t)t0 * BB + b_glob) * G4 + u0g * 4);
        pg[0] = src[0]; pg[1] = src[1];
    }

    // precompute DSMEM push addresses (local byte offsets; rank-mapped per store)
    const uint32_t laddr_off = (m_loc * RLDS + u0g) * 2;

    CLUSTER_SYNC();   // W + zeroed A visible cluster-wide

    const uint32_t aoff = ((lane & 15) * RLDS + (lane >> 4) * 8) * 2;
    const uint32_t bbase = (uint32_t)(wn * 16 * RLDS * 2);

    for (int s = 0; s < TT; s++) {
        int t = dir ? (TT - 1 - s) : s;
        const uint32_t pA_H = smb + ((s & 1) ? OA_H1 : OA_H0);
        const uint32_t pA_L = smb + ((s & 1) ? OA_L1 : OA_L0);

        // mma: S[16 x 128] = h @ Whh_slice^T (2-term fp16 split)
        float acc[2][4];
#pragma unroll
        for (int ni = 0; ni < 2; ni++)
#pragma unroll
            for (int q = 0; q < 4; q++) acc[ni][q] = 0.f;

#pragma unroll 4
        for (int k0 = 0; k0 < HH; k0 += 16) {
            uint32_t koff = aoff + k0 * 2;
            uint32_t ah[4], al[4], bh[4];
            ldm4(ah, pA_H + koff);
            ldm4(al, pA_L + koff);
            ldm4(bh, smb + OW_S + bbase + koff);
            mma_f16(acc[0], ah, bh[0], bh[2]);
            mma_f16(acc[0], al, bh[0], bh[2]);
            mma_f16(acc[1], ah, bh[1], bh[3]);
            mma_f16(acc[1], al, bh[1], bh[3]);
        }

        // accumulators -> smem S
#pragma unroll
        for (int ni = 0; ni < 2; ni++) {
            int col = wn * 16 + ni * 8 + tig * 2;
            *(float2*)&S[gid * 132 + col] = make_float2(acc[ni][0], acc[ni][1]);
            *(float2*)&S[(gid + 8) * 132 + col] = make_float2(acc[ni][2], acc[ni][3]);
        }
        __syncthreads();

        // pointwise: (m_loc, units u0g, u0g+1)
        const bool val = (t < len);
        __half hh[2], hl[2], oh[2], ol[2];
        float of2[2];
#pragma unroll
        for (int j = 0; j < 2; j++) {
            float4 sg = *(const float4*)&S[m_loc * 132 + (ug * 2 + j) * 4];
            float4 g = pg[j];
            float gi = sigmfast(sg.x + g.x);
            float gf = sigmfast(sg.y + g.y);
            float gg = tanhfast(sg.z + g.z);
            float go = sigmfast(sg.w + g.w);
            float cn = gf * cs[j] + gi * gg;
            float hn = go * tanhfast(cn);
            if (val) { cs[j] = cn; hs[j] = hn; }
            float ov = val ? hn : 0.f;
            split_f16(hs[j], hh[j], hl[j]);
            split_f16(ov, oh[j], ol[j]);
            of2[j] = ov;
        }
        // push h (hi/lo, 2 units = 1 u32 each) into all 8 cluster CTAs' A[p^1]
        {
            uint32_t vh = (uint32_t)__half_as_ushort(hh[0]) |
                          ((uint32_t)__half_as_ushort(hh[1]) << 16);
            uint32_t vl = (uint32_t)__half_as_ushort(hl[0]) |
                          ((uint32_t)__half_as_ushort(hl[1]) << 16);
            uint32_t la_h = smb + ((s & 1) ? OA_H0 : OA_H1) + laddr_off;
            uint32_t la_l = smb + ((s & 1) ? OA_L0 : OA_L1) + laddr_off;
#pragma unroll
            for (uint32_t r = 0; r < 8; r++) {
                st_clu(mapa_u32(la_h, r), vh);
                st_clu(mapa_u32(la_l, r), vl);
            }
        }

        // off critical path: layer outputs + next-step gate prefetch
        if (layer == 0) {
            size_t off = ((size_t)t * BB + b_glob) * DIN + dir * HH + u0g;
            *(uint32_t*)(g_i2h + off) = (uint32_t)__half_as_ushort(oh[0]) |
                                        ((uint32_t)__half_as_ushort(oh[1]) << 16);
            *(uint32_t*)(g_i2l + off) = (uint32_t)__half_as_ushort(ol[0]) |
                                        ((uint32_t)__half_as_ushort(ol[1]) << 16);
        } else {
            *(float2*)(dout + ((size_t)b_glob * TT + t) * 512 + dir * HH + u0g) =
                make_float2(of2[0], of2[1]);
        }
        if (s + 1 < TT) {
            int t2 = dir ? (TT - 2 - s) : (s + 1);
            const float4* src = (const float4*)(xpbase + ((size_t)t2 * BB + b_glob) * G4 + u0g * 4);
            pg[0] = src[0]; pg[1] = src[1];
        }

        CLUSTER_SYNC();   // pushes visible everywhere; also block barrier for S
    }

    // final h_n / c_n
    {
        size_t o = (size_t)((layer * 2 + dir) * BB + b_glob) * HH + u0g;
        *(float2*)(dout + HN_OFF + o) = make_float2(hs[0], hs[1]);
        *(float2*)(dout + CN_OFF + o) = make_float2(cs[0], cs[1]);
    }
}

// ---------------- launch -----------------------------------------------------
extern "C" void kernel_launch(void* const* d_in, const int* in_sizes, int n_in,
                              void* d_out, int out_size)
{
    const float* x   = (const float*)d_in[0];
    const int*   len = (const int*)d_in[1];
    const float* Wih = (const float*)d_in[2];
    const float* Whh = (const float*)d_in[3];
    const float* bih = (const float*)d_in[4];
    const float* bhh = (const float*)d_in[5];
    float* out = (float*)d_out;

    cudaFuncSetAttribute(k_lstm, cudaFuncAttributeMaxDynamicSharedMemorySize, SM_REC);
    cudaFuncSetAttribute(k_gemm_tc, cudaFuncAttributeMaxDynamicSharedMemorySize, SM_GEMM);

    k_split_x<<<(MM * (DIN / 4) + 255) / 256, 256>>>(x);
    k_split_w<<<(4 * G4 * (DIN / 4) + 255) / 256, 256>>>(Wih, bih, bhh);

    k_gemm_tc<<<dim3(G4 / 128, MM / 128, 2), 256, SM_GEMM>>>(0);
    k_lstm<<<128, 256, SM_REC>>>(Whh, len, out, 0);
    k_gemm_tc<<<dim3(G4 / 128, MM / 128, 2), 256, SM_GEMM>>>(1);
    k_lstm<<<128, 256, SM_REC>>>(Whh, len, out, 1);
}

// round 8
// speedup vs baseline: 3.8538x; 1.4712x over previous
#include <cuda_runtime.h>
#include <cuda_fp16.h>
#include <cstdint>

#define BB   128      // batch
#define TT   512      // time
#define DIN  512      // input dim (also 2H for layer 1)
#define HH   256      // hidden
#define G4   1024     // 4*H
#define MM   (TT*BB)  // 65536 rows of A

#define HN_OFF 33554432ULL              // B*T*512
#define CN_OFF (HN_OFF + 131072ULL)     // + 4*B*H

// ---------------- device scratch (static, no runtime alloc) ----------------
__device__ __align__(256) __half g_xh[(size_t)MM * DIN];   // x hi (T,B,D)
__device__ __align__(256) __half g_xl[(size_t)MM * DIN];   // x lo
__device__ __align__(256) __half g_i2h[(size_t)MM * DIN];  // layer-1 input hi
__device__ __align__(256) __half g_i2l[(size_t)MM * DIN];  // layer-1 input lo
__device__ __align__(256) __half g_w[4ULL * G4 * DIN];     // permuted W_ih (fp16)
__device__ __align__(256) float g_bias[4 * G4];            // permuted b_ih+b_hh
__device__ __align__(256) float g_xproj[2ULL * TT * BB * G4];  // gate preacts

// ---------------- small helpers --------------------------------------------
__device__ __forceinline__ float tanhfast(float x) {
    float y; asm("tanh.approx.f32 %0, %1;" : "=f"(y) : "f"(x)); return y;
}
__device__ __forceinline__ float sigmfast(float x) {
    return fmaf(0.5f, tanhfast(0.5f * x), 0.5f);
}
__device__ __forceinline__ uint32_t smem_u32(const void* p) {
    uint32_t a;
    asm("{ .reg .u64 t; cvta.to.shared.u64 t, %1; cvt.u32.u64 %0, t; }" : "=r"(a) : "l"(p));
    return a;
}
__device__ __forceinline__ void split_f16(float v, __half& h, __half& l) {
    h = __float2half_rn(v);
    l = __float2half_rn(v - __half2float(h));
}

// ---------------- mma.sync / ldmatrix / cp.async / cluster wrappers ---------
__device__ __forceinline__ void ldm4(uint32_t* r, uint32_t addr) {
    asm volatile("ldmatrix.sync.aligned.m8n8.x4.shared.b16 {%0,%1,%2,%3}, [%4];"
                 : "=r"(r[0]), "=r"(r[1]), "=r"(r[2]), "=r"(r[3]) : "r"(addr));
}
__device__ __forceinline__ void mma_f16(float* d, const uint32_t* a,
                                        uint32_t b0, uint32_t b1) {
    asm volatile(
        "mma.sync.aligned.m16n8k16.row.col.f32.f16.f16.f32 "
        "{%0,%1,%2,%3}, {%4,%5,%6,%7}, {%8,%9}, {%0,%1,%2,%3};"
        : "+f"(d[0]), "+f"(d[1]), "+f"(d[2]), "+f"(d[3])
        : "r"(a[0]), "r"(a[1]), "r"(a[2]), "r"(a[3]), "r"(b0), "r"(b1));
}
__device__ __forceinline__ void cpasync16(uint32_t dst, const void* src) {
    asm volatile("cp.async.cg.shared.global [%0], [%1], 16;" :: "r"(dst), "l"(src));
}
#define CP_COMMIT() asm volatile("cp.async.commit_group;" ::: "memory")
#define CP_WAIT(n)  asm volatile("cp.async.wait_group %0;" :: "n"(n) : "memory")
#define CLU_ARRIVE() asm volatile("barrier.cluster.arrive.aligned;" ::: "memory")
#define CLU_WAIT()   asm volatile("barrier.cluster.wait.aligned;" ::: "memory")
__device__ __forceinline__ uint32_t mapa_u32(uint32_t laddr, uint32_t rank) {
    uint32_t r;
    asm volatile("mapa.shared::cluster.u32 %0, %1, %2;" : "=r"(r) : "r"(laddr), "r"(rank));
    return r;
}
__device__ __forceinline__ void st_clu(uint32_t addr, uint32_t v) {
    asm volatile("st.shared::cluster.u32 [%0], %1;" :: "r"(addr), "r"(v));
}

// ---------------- split + transpose x: (B,T,D) fp32 -> (T,B,D) fp16 hi/lo ---
__global__ void k_split_x(const float* __restrict__ x)
{
    int i = blockIdx.x * blockDim.x + threadIdx.x;       // float4 index
    const int N4 = MM * (DIN / 4);
    if (i >= N4) return;
    int k4 = i & 127;
    int bt = i >> 7;
    int t = bt & (TT - 1);
    int b = bt >> 9;
    float4 v = ((const float4*)x)[i];
    __half h[4], l[4];
    split_f16(v.x, h[0], l[0]); split_f16(v.y, h[1], l[1]);
    split_f16(v.z, h[2], l[2]); split_f16(v.w, h[3], l[3]);
    size_t off = ((size_t)t * BB + b) * DIN + k4 * 4;
    *(uint2*)(g_xh + off) = *(uint2*)h;
    *(uint2*)(g_xl + off) = *(uint2*)l;
}

// ---------------- convert + permute weights (fp16 single) -------------------
__global__ void k_split_w(const float* __restrict__ Wih, const float* __restrict__ bih,
                          const float* __restrict__ bhh)
{
    int i = blockIdx.x * blockDim.x + threadIdx.x;       // (ld, n, k4)
    if (i >= 4 * G4 * (DIN / 4)) return;
    int k4 = i & 127;
    int rest = i >> 7;
    int n = rest & (G4 - 1);
    int ld = rest >> 10;
    int r = (n & 3) * HH + (n >> 2);
    float4 v = *(const float4*)(Wih + ((size_t)ld * G4 + r) * DIN + k4 * 4);
    __half h[4];
    h[0] = __float2half_rn(v.x); h[1] = __float2half_rn(v.y);
    h[2] = __float2half_rn(v.z); h[3] = __float2half_rn(v.w);
    size_t off = ((size_t)ld * G4 + n) * DIN + k4 * 4;
    *(uint2*)(g_w + off) = *(uint2*)h;
    if (k4 == 0)
        g_bias[ld * G4 + n] = bih[ld * G4 + r] + bhh[ld * G4 + r];
}

// ---------------- mma.sync input-projection GEMM (2-term fp16, 3-stage) ------
#define KC     32
#define NCH    (DIN / KC)                  // 16 chunks
#define LDS_T  40
#define ARR_B  (128 * LDS_T * 2)           // 10240
#define STG_B  (3 * ARR_B)                 // 30720
#define SMO_BIAS  0
#define SMO_TILES 512
#define SM_GEMM   (SMO_TILES + 3 * STG_B)  // 92672

__global__ void __launch_bounds__(256, 2) k_gemm_tc(int layer)
{
    extern __shared__ char smx[];
    const uint32_t smb = smem_u32(smx);
    const int tid = threadIdx.x;
    const int lane = tid & 31;
    const int w   = tid >> 5;
    const int wm  = w & 1;
    const int wn  = w >> 1;
    const int dir = blockIdx.z;
    const int mb  = blockIdx.y * 128;
    const int nb  = blockIdx.x * 128;

    const __half* Ah = layer ? g_i2h : g_xh;
    const __half* Al = layer ? g_i2l : g_xl;
    const __half* Wd = g_w + (size_t)(layer * 2 + dir) * G4 * DIN;

    float* bs = (float*)(smx + SMO_BIAS);
    if (tid < 128) bs[tid] = g_bias[(layer * 2 + dir) * G4 + nb + tid];

    // stage issuer: 3 arrays x 128 rows x 4 chunks = 1536 cps, 6 per thread
    auto issue_stage = [&](int ch) {
        const int kc = ch * KC;
        const uint32_t sb = smb + SMO_TILES + (ch % 3) * STG_B;
#pragma unroll
        for (int j = 0; j < 6; j++) {
            int c = tid + j * 256;
            int arr = c >> 9, rem = c & 511, row = rem >> 2, ck = rem & 3;
            uint32_t dst = sb + arr * ARR_B + row * (LDS_T * 2) + ck * 16;
            const __half* src;
            if (arr == 0)      src = Ah + (size_t)(mb + row) * DIN + kc + ck * 8;
            else if (arr == 1) src = Al + (size_t)(mb + row) * DIN + kc + ck * 8;
            else               src = Wd + (size_t)(nb + row) * DIN + kc + ck * 8;
            cpasync16(dst, src);
        }
        CP_COMMIT();
    };

    issue_stage(0);
    issue_stage(1);

    float acc[4][4][4];
#pragma unroll
    for (int mi = 0; mi < 4; mi++)
#pragma unroll
        for (int ni = 0; ni < 4; ni++)
#pragma unroll
            for (int q = 0; q < 4; q++) acc[mi][ni][q] = 0.f;

    for (int ch = 0; ch < NCH; ch++) {
        if (ch + 2 < NCH) { issue_stage(ch + 2); CP_WAIT(2); }
        else if (ch + 1 < NCH) { CP_WAIT(1); }
        else { CP_WAIT(0); }
        __syncthreads();

        const uint32_t sA_h = smb + SMO_TILES + (ch % 3) * STG_B;
        const uint32_t sA_l = sA_h + ARR_B;
        const uint32_t sB   = sA_h + 2 * ARR_B;

#pragma unroll
        for (int ks = 0; ks < 2; ks++) {
            const int k0 = ks * 16;
            const uint32_t aoff = ((lane & 15) * LDS_T + k0 + (lane >> 4) * 8) * 2;
            uint32_t ah[4][4], al[4][4];
#pragma unroll
            for (int mi = 0; mi < 4; mi++) {
                uint32_t ro = (wm * 64 + mi * 16) * (LDS_T * 2);
                ldm4(ah[mi], sA_h + ro + aoff);
                ldm4(al[mi], sA_l + ro + aoff);
            }
            uint32_t bh[2][4];
#pragma unroll
            for (int nj = 0; nj < 2; nj++) {
                uint32_t ro = (wn * 32 + nj * 16) * (LDS_T * 2);
                ldm4(bh[nj], sB + ro + aoff);
            }
#pragma unroll
            for (int mi = 0; mi < 4; mi++)
#pragma unroll
                for (int ni = 0; ni < 4; ni++) {
                    int nj = ni >> 1, hf = ni & 1;
                    mma_f16(acc[mi][ni], ah[mi], bh[nj][hf], bh[nj][hf + 2]);
                    mma_f16(acc[mi][ni], al[mi], bh[nj][hf], bh[nj][hf + 2]);
                }
        }
        __syncthreads();   // all warps done with buffer ch%3 before reissue
    }

    float* xp = g_xproj + (size_t)dir * TT * BB * G4;
    const int gid = lane >> 2, tig = lane & 3;
#pragma unroll
    for (int mi = 0; mi < 4; mi++) {
#pragma unroll
        for (int ni = 0; ni < 4; ni++) {
            int col = wn * 32 + ni * 8 + tig * 2;
            float b0 = bs[col], b1 = bs[col + 1];
            int r0 = mb + wm * 64 + mi * 16 + gid;
            float2 v0 = make_float2(acc[mi][ni][0] + b0, acc[mi][ni][1] + b1);
            float2 v1 = make_float2(acc[mi][ni][2] + b0, acc[mi][ni][3] + b1);
            *(float2*)(xp + (size_t)r0 * G4 + nb + col) = v0;
            *(float2*)(xp + (size_t)(r0 + 8) * G4 + nb + col) = v1;
        }
    }
}

// ---------------- recurrent persistent kernel (cluster + DSMEM, 1-term h) ----
// grid = 2 dir x 8 bgroup (M=16) x 8 nslice (N=128).  Cluster = the 8 nslices.
#define RLDS  264                          // padded row stride (fp16 elems)
#define OW_S  0                            // W slice: 128 x 256 fp16 = 67584
#define AB_SZ (16 * RLDS * 2)              // 8448 per A buffer
#define OA_H0 (OW_S + 128 * RLDS * 2)      // 67584
#define OA_H1 (OA_H0 + AB_SZ)              // 76032
#define OS_S  (OA_H1 + AB_SZ)              // 84480  S: 16 x 132 f32
#define SM_REC (OS_S + 16 * 132 * 4)       // 92928

__global__ void __launch_bounds__(256) __cluster_dims__(8, 1, 1)
k_lstm(const float* __restrict__ Whh, const int* __restrict__ lengths,
       float* __restrict__ dout, int layer)
{
    extern __shared__ char smx[];
    const uint32_t smb = smem_u32(smx);
    float* S = (float*)(smx + OS_S);

    const int cid = blockIdx.x >> 3;      // cluster id 0..15
    const int dir = cid >> 3;             // 0..1
    const int mg  = cid & 7;              // batch group 0..7 (M=16)
    const int ns  = blockIdx.x & 7;       // n-slice (== cluster ctarank)
    const int tid = threadIdx.x;
    const int lane = tid & 31;
    const int wn  = tid >> 5;             // warp 0..7 -> 16 gate cols each
    const int gid = lane >> 2, tig = lane & 3;

    const float* W = Whh + (size_t)(layer * 2 + dir) * G4 * HH;

    // resident W_hh slice (128 gate cols x 256) -> smem fp16, once
    for (int idx = tid; idx < 128 * 256; idx += 256) {
        int nl = idx >> 8; int k = idx & 255;
        int n = ns * 128 + nl;
        int row = (n & 3) * HH + (n >> 2);
        *(__half*)(smx + OW_S + (nl * RLDS + k) * 2) = __float2half_rn(W[(size_t)row * HH + k]);
    }
    // zero both parities of A
    for (int idx = tid; idx < 2 * AB_SZ / 4; idx += 256)
        *(uint32_t*)(smx + OA_H0 + idx * 4) = 0;

    // per-thread pointwise mapping: batch m = tid&15, 2 units
    const int m_loc = tid & 15;
    const int ug = tid >> 4;              // 0..15
    const int b_glob = mg * 16 + m_loc;
    const int u0g = ns * 32 + ug * 2;     // global unit index (col in A)
    const int len = lengths[b_glob];

    float cs[2] = {0.f, 0.f};
    float hs[2] = {0.f, 0.f};

    const float* xpbase = g_xproj + (size_t)dir * TT * BB * G4;

    float4 pg[2];
    {
        int t0 = dir ? (TT - 1) : 0;
        const float4* src = (const float4*)(xpbase + ((size_t)t0 * BB + b_glob) * G4 + u0g * 4);
        pg[0] = src[0]; pg[1] = src[1];
    }

    const uint32_t laddr_off = (m_loc * RLDS + u0g) * 2;

    CLU_ARRIVE(); CLU_WAIT();   // W + zeroed A visible cluster-wide

    const uint32_t aoff = ((lane & 15) * RLDS + (lane >> 4) * 8) * 2;
    const uint32_t bbase = (uint32_t)(wn * 16 * RLDS * 2);

    for (int s = 0; s < TT; s++) {
        int t = dir ? (TT - 1 - s) : s;
        const uint32_t pA = smb + ((s & 1) ? OA_H1 : OA_H0);

        // mma: S[16 x 128] = h @ Whh_slice^T (fp16 h-hi only)
        float acc[2][4];
#pragma unroll
        for (int ni = 0; ni < 2; ni++)
#pragma unroll
            for (int q = 0; q < 4; q++) acc[ni][q] = 0.f;

#pragma unroll 8
        for (int k0 = 0; k0 < HH; k0 += 16) {
            uint32_t koff = aoff + k0 * 2;
            uint32_t ah[4], bh[4];
            ldm4(ah, pA + koff);
            ldm4(bh, smb + OW_S + bbase + koff);
            mma_f16(acc[0], ah, bh[0], bh[2]);
            mma_f16(acc[1], ah, bh[1], bh[3]);
        }

        // accumulators -> smem S
#pragma unroll
        for (int ni = 0; ni < 2; ni++) {
            int col = wn * 16 + ni * 8 + tig * 2;
            *(float2*)&S[gid * 132 + col] = make_float2(acc[ni][0], acc[ni][1]);
            *(float2*)&S[(gid + 8) * 132 + col] = make_float2(acc[ni][2], acc[ni][3]);
        }
        __syncthreads();

        // pointwise: (m_loc, units u0g, u0g+1)
        const bool val = (t < len);
        __half oh[2], ol[2];
        float of2[2];
#pragma unroll
        for (int j = 0; j < 2; j++) {
            float4 sg = *(const float4*)&S[m_loc * 132 + (ug * 2 + j) * 4];
            float4 g = pg[j];
            float gi = sigmfast(sg.x + g.x);
            float gf = sigmfast(sg.y + g.y);
            float gg = tanhfast(sg.z + g.z);
            float go = sigmfast(sg.w + g.w);
            float cn = gf * cs[j] + gi * gg;
            float hn = go * tanhfast(cn);
            if (val) { cs[j] = cn; hs[j] = hn; }
            float ov = val ? hn : 0.f;
            split_f16(ov, oh[j], ol[j]);
            of2[j] = ov;
        }
        // push h-hi (2 units = 1 u32) into all 8 cluster CTAs' A[p^1]
        {
            uint32_t vh = (uint32_t)__half_as_ushort(__float2half_rn(hs[0])) |
                          ((uint32_t)__half_as_ushort(__float2half_rn(hs[1])) << 16);
            uint32_t la = smb + ((s & 1) ? OA_H0 : OA_H1) + laddr_off;
#pragma unroll
            for (uint32_t r = 0; r < 8; r++)
                st_clu(mapa_u32(la, r), vh);
        }

        CLU_ARRIVE();   // pushes ordered/released; overlap global work with skew

        if (layer == 0) {
            size_t off = ((size_t)t * BB + b_glob) * DIN + dir * HH + u0g;
            *(uint32_t*)(g_i2h + off) = (uint32_t)__half_as_ushort(oh[0]) |
                                        ((uint32_t)__half_as_ushort(oh[1]) << 16);
            *(uint32_t*)(g_i2l + off) = (uint32_t)__half_as_ushort(ol[0]) |
                                        ((uint32_t)__half_as_ushort(ol[1]) << 16);
        } else {
            *(float2*)(dout + ((size_t)b_glob * TT + t) * 512 + dir * HH + u0g) =
                make_float2(of2[0], of2[1]);
        }
        if (s + 1 < TT) {
            int t2 = dir ? (TT - 2 - s) : (s + 1);
            const float4* src = (const float4*)(xpbase + ((size_t)t2 * BB + b_glob) * G4 + u0g * 4);
            pg[0] = src[0]; pg[1] = src[1];
        }

        CLU_WAIT();     // peers' pushes visible; also full block barrier
    }

    // final h_n / c_n
    {
        size_t o = (size_t)((layer * 2 + dir) * BB + b_glob) * HH + u0g;
        *(float2*)(dout + HN_OFF + o) = make_float2(hs[0], hs[1]);
        *(float2*)(dout + CN_OFF + o) = make_float2(cs[0], cs[1]);
    }
}

// ---------------- launch -----------------------------------------------------
extern "C" void kernel_launch(void* const* d_in, const int* in_sizes, int n_in,
                              void* d_out, int out_size)
{
    const float* x   = (const float*)d_in[0];
    const int*   len = (const int*)d_in[1];
    const float* Wih = (const float*)d_in[2];
    const float* Whh = (const float*)d_in[3];
    const float* bih = (const float*)d_in[4];
    const float* bhh = (const float*)d_in[5];
    float* out = (float*)d_out;

    cudaFuncSetAttribute(k_lstm, cudaFuncAttributeMaxDynamicSharedMemorySize, SM_REC);
    cudaFuncSetAttribute(k_gemm_tc, cudaFuncAttributeMaxDynamicSharedMemorySize, SM_GEMM);

    k_split_x<<<(MM * (DIN / 4) + 255) / 256, 256>>>(x);
    k_split_w<<<(4 * G4 * (DIN / 4) + 255) / 256, 256>>>(Wih, bih, bhh);

    k_gemm_tc<<<dim3(G4 / 128, MM / 128, 2), 256, SM_GEMM>>>(0);
    k_lstm<<<128, 256, SM_REC>>>(Whh, len, out, 0);
    k_gemm_tc<<<dim3(G4 / 128, MM / 128, 2), 256, SM_GEMM>>>(1);
    k_lstm<<<128, 256, SM_REC>>>(Whh, len, out, 1);
}

// round 9
// speedup vs baseline: 5.2888x; 1.3724x over previous
#include <cuda_runtime.h>
#include <cuda_fp16.h>
#include <cstdint>

#define BB   128      // batch
#define TT   512      // time
#define DIN  512      // input dim (also 2H for layer 1)
#define HH   256      // hidden
#define G4   1024     // 4*H
#define MM   (TT*BB)  // 65536 rows of A

#define HN_OFF 33554432ULL              // B*T*512
#define CN_OFF (HN_OFF + 131072ULL)     // + 4*B*H

// ---------------- device scratch (static, no runtime alloc) ----------------
__device__ __align__(256) __half g_xh[(size_t)MM * DIN];   // x fp16 (T,B,D)
__device__ __align__(256) __half g_i2h[(size_t)MM * DIN];  // layer-1 input fp16
__device__ __align__(256) __half g_w[4ULL * G4 * DIN];     // permuted W_ih (fp16)
__device__ __align__(256) float g_bias[4 * G4];            // permuted b_ih+b_hh
__device__ __align__(256) float g_xproj[2ULL * TT * BB * G4];  // gate preacts

// ---------------- small helpers --------------------------------------------
__device__ __forceinline__ float tanhfast(float x) {
    float y; asm("tanh.approx.f32 %0, %1;" : "=f"(y) : "f"(x)); return y;
}
__device__ __forceinline__ float sigmfast(float x) {
    return fmaf(0.5f, tanhfast(0.5f * x), 0.5f);
}
__device__ __forceinline__ uint32_t smem_u32(const void* p) {
    uint32_t a;
    asm("{ .reg .u64 t; cvta.to.shared.u64 t, %1; cvt.u32.u64 %0, t; }" : "=r"(a) : "l"(p));
    return a;
}

// ---------------- mma.sync / ldmatrix / cp.async / cluster wrappers ---------
__device__ __forceinline__ void ldm4(uint32_t* r, uint32_t addr) {
    asm volatile("ldmatrix.sync.aligned.m8n8.x4.shared.b16 {%0,%1,%2,%3}, [%4];"
                 : "=r"(r[0]), "=r"(r[1]), "=r"(r[2]), "=r"(r[3]) : "r"(addr));
}
__device__ __forceinline__ void mma_f16(float* d, const uint32_t* a,
                                        uint32_t b0, uint32_t b1) {
    asm volatile(
        "mma.sync.aligned.m16n8k16.row.col.f32.f16.f16.f32 "
        "{%0,%1,%2,%3}, {%4,%5,%6,%7}, {%8,%9}, {%0,%1,%2,%3};"
        : "+f"(d[0]), "+f"(d[1]), "+f"(d[2]), "+f"(d[3])
        : "r"(a[0]), "r"(a[1]), "r"(a[2]), "r"(a[3]), "r"(b0), "r"(b1));
}
__device__ __forceinline__ void cpasync16(uint32_t dst, const void* src) {
    asm volatile("cp.async.cg.shared.global [%0], [%1], 16;" :: "r"(dst), "l"(src));
}
#define CP_COMMIT() asm volatile("cp.async.commit_group;" ::: "memory")
#define CP_WAIT(n)  asm volatile("cp.async.wait_group %0;" :: "n"(n) : "memory")
#define CLU_ARRIVE() asm volatile("barrier.cluster.arrive.aligned;" ::: "memory")
#define CLU_WAIT()   asm volatile("barrier.cluster.wait.aligned;" ::: "memory")
__device__ __forceinline__ uint32_t mapa_u32(uint32_t laddr, uint32_t rank) {
    uint32_t r;
    asm volatile("mapa.shared::cluster.u32 %0, %1, %2;" : "=r"(r) : "r"(laddr), "r"(rank));
    return r;
}
__device__ __forceinline__ void st_clu(uint32_t addr, uint32_t v) {
    asm volatile("st.shared::cluster.u32 [%0], %1;" :: "r"(addr), "r"(v));
}

// ---------------- transpose x: (B,T,D) fp32 -> (T,B,D) fp16 ------------------
__global__ void k_split_x(const float* __restrict__ x)
{
    int i = blockIdx.x * blockDim.x + threadIdx.x;       // float4 index
    const int N4 = MM * (DIN / 4);
    if (i >= N4) return;
    int k4 = i & 127;
    int bt = i >> 7;
    int t = bt & (TT - 1);
    int b = bt >> 9;
    float4 v = ((const float4*)x)[i];
    __half h[4];
    h[0] = __float2half_rn(v.x); h[1] = __float2half_rn(v.y);
    h[2] = __float2half_rn(v.z); h[3] = __float2half_rn(v.w);
    size_t off = ((size_t)t * BB + b) * DIN + k4 * 4;
    *(uint2*)(g_xh + off) = *(uint2*)h;
}

// ---------------- convert + permute weights (fp16 single) -------------------
__global__ void k_split_w(const float* __restrict__ Wih, const float* __restrict__ bih,
                          const float* __restrict__ bhh)
{
    int i = blockIdx.x * blockDim.x + threadIdx.x;       // (ld, n, k4)
    if (i >= 4 * G4 * (DIN / 4)) return;
    int k4 = i & 127;
    int rest = i >> 7;
    int n = rest & (G4 - 1);
    int ld = rest >> 10;
    int r = (n & 3) * HH + (n >> 2);
    float4 v = *(const float4*)(Wih + ((size_t)ld * G4 + r) * DIN + k4 * 4);
    __half h[4];
    h[0] = __float2half_rn(v.x); h[1] = __float2half_rn(v.y);
    h[2] = __float2half_rn(v.z); h[3] = __float2half_rn(v.w);
    size_t off = ((size_t)ld * G4 + n) * DIN + k4 * 4;
    *(uint2*)(g_w + off) = *(uint2*)h;
    if (k4 == 0)
        g_bias[ld * G4 + n] = bih[ld * G4 + r] + bhh[ld * G4 + r];
}

// ---------------- mma.sync input-projection GEMM (1-term fp16, 3-stage) ------
#define KC     32
#define NCH    (DIN / KC)                  // 16 chunks
#define LDS_T  40
#define ARR_B  (128 * LDS_T * 2)           // 10240
#define STG_B  (2 * ARR_B)                 // 20480  (A + W)
#define SMO_BIAS  0
#define SMO_TILES 512
#define SM_GEMM   (SMO_TILES + 3 * STG_B)  // 61952

__global__ void __launch_bounds__(256, 2) k_gemm_tc(int layer)
{
    extern __shared__ char smx[];
    const uint32_t smb = smem_u32(smx);
    const int tid = threadIdx.x;
    const int lane = tid & 31;
    const int w   = tid >> 5;
    const int wm  = w & 1;
    const int wn  = w >> 1;
    const int dir = blockIdx.z;
    const int mb  = blockIdx.y * 128;
    const int nb  = blockIdx.x * 128;

    const __half* Ah = layer ? g_i2h : g_xh;
    const __half* Wd = g_w + (size_t)(layer * 2 + dir) * G4 * DIN;

    float* bs = (float*)(smx + SMO_BIAS);
    if (tid < 128) bs[tid] = g_bias[(layer * 2 + dir) * G4 + nb + tid];

    // stage issuer: 2 arrays x 128 rows x 4 chunks = 1024 cps, 4 per thread
    auto issue_stage = [&](int ch) {
        const int kc = ch * KC;
        const uint32_t sb = smb + SMO_TILES + (ch % 3) * STG_B;
#pragma unroll
        for (int j = 0; j < 4; j++) {
            int c = tid + j * 256;
            int arr = c >> 9, rem = c & 511, row = rem >> 2, ck = rem & 3;
            uint32_t dst = sb + arr * ARR_B + row * (LDS_T * 2) + ck * 16;
            const __half* src = (arr == 0)
                ? Ah + (size_t)(mb + row) * DIN + kc + ck * 8
                : Wd + (size_t)(nb + row) * DIN + kc + ck * 8;
            cpasync16(dst, src);
        }
        CP_COMMIT();
    };

    issue_stage(0);
    issue_stage(1);

    float acc[4][4][4];
#pragma unroll
    for (int mi = 0; mi < 4; mi++)
#pragma unroll
        for (int ni = 0; ni < 4; ni++)
#pragma unroll
            for (int q = 0; q < 4; q++) acc[mi][ni][q] = 0.f;

    for (int ch = 0; ch < NCH; ch++) {
        if (ch + 2 < NCH) { issue_stage(ch + 2); CP_WAIT(2); }
        else if (ch + 1 < NCH) { CP_WAIT(1); }
        else { CP_WAIT(0); }
        __syncthreads();

        const uint32_t sA = smb + SMO_TILES + (ch % 3) * STG_B;
        const uint32_t sB = sA + ARR_B;

#pragma unroll
        for (int ks = 0; ks < 2; ks++) {
            const int k0 = ks * 16;
            const uint32_t aoff = ((lane & 15) * LDS_T + k0 + (lane >> 4) * 8) * 2;
            uint32_t ah[4][4];
#pragma unroll
            for (int mi = 0; mi < 4; mi++) {
                uint32_t ro = (wm * 64 + mi * 16) * (LDS_T * 2);
                ldm4(ah[mi], sA + ro + aoff);
            }
            uint32_t bh[2][4];
#pragma unroll
            for (int nj = 0; nj < 2; nj++) {
                uint32_t ro = (wn * 32 + nj * 16) * (LDS_T * 2);
                ldm4(bh[nj], sB + ro + aoff);
            }
#pragma unroll
            for (int mi = 0; mi < 4; mi++)
#pragma unroll
                for (int ni = 0; ni < 4; ni++) {
                    int nj = ni >> 1, hf = ni & 1;
                    mma_f16(acc[mi][ni], ah[mi], bh[nj][hf], bh[nj][hf + 2]);
                }
        }
        __syncthreads();
    }

    float* xp = g_xproj + (size_t)dir * TT * BB * G4;
    const int gid = lane >> 2, tig = lane & 3;
#pragma unroll
    for (int mi = 0; mi < 4; mi++) {
#pragma unroll
        for (int ni = 0; ni < 4; ni++) {
            int col = wn * 32 + ni * 8 + tig * 2;
            float b0 = bs[col], b1 = bs[col + 1];
            int r0 = mb + wm * 64 + mi * 16 + gid;
            float2 v0 = make_float2(acc[mi][ni][0] + b0, acc[mi][ni][1] + b1);
            float2 v1 = make_float2(acc[mi][ni][2] + b0, acc[mi][ni][3] + b1);
            *(float2*)(xp + (size_t)r0 * G4 + nb + col) = v0;
            *(float2*)(xp + (size_t)(r0 + 8) * G4 + nb + col) = v1;
        }
    }
}

// ---------------- recurrent persistent kernel (cluster + DSMEM) --------------
// grid = 2 dir x 8 bgroup (M=16) x 8 nslice (N=128).  Cluster = the 8 nslices.
// W_hh fragments hoisted into registers (loop-invariant).
#define RLDS  264                          // padded row stride (fp16 elems)
#define OW_S  0                            // W slice: 128 x 256 fp16 = 67584
#define AB_SZ (16 * RLDS * 2)              // 8448 per A buffer
#define OA_H0 (OW_S + 128 * RLDS * 2)      // 67584
#define OA_H1 (OA_H0 + AB_SZ)              // 76032
#define OS_S  (OA_H1 + AB_SZ)              // 84480  S: 16 x 132 f32
#define SM_REC (OS_S + 16 * 132 * 4)       // 92928

__global__ void __launch_bounds__(256) __cluster_dims__(8, 1, 1)
k_lstm(const float* __restrict__ Whh, const int* __restrict__ lengths,
       float* __restrict__ dout, int layer)
{
    extern __shared__ char smx[];
    const uint32_t smb = smem_u32(smx);
    float* S = (float*)(smx + OS_S);

    const int cid = blockIdx.x >> 3;      // cluster id 0..15
    const int dir = cid >> 3;             // 0..1
    const int mg  = cid & 7;              // batch group 0..7 (M=16)
    const int ns  = blockIdx.x & 7;       // n-slice (== cluster ctarank)
    const int tid = threadIdx.x;
    const int lane = tid & 31;
    const int wn  = tid >> 5;             // warp 0..7 -> 16 gate cols each
    const int gid = lane >> 2, tig = lane & 3;

    const float* W = Whh + (size_t)(layer * 2 + dir) * G4 * HH;

    // resident W_hh slice (128 gate cols x 256) -> smem fp16, once
    for (int idx = tid; idx < 128 * 256; idx += 256) {
        int nl = idx >> 8; int k = idx & 255;
        int n = ns * 128 + nl;
        int row = (n & 3) * HH + (n >> 2);
        *(__half*)(smx + OW_S + (nl * RLDS + k) * 2) = __float2half_rn(W[(size_t)row * HH + k]);
    }
    // zero both parities of A
    for (int idx = tid; idx < 2 * AB_SZ / 4; idx += 256)
        *(uint32_t*)(smx + OA_H0 + idx * 4) = 0;
    __syncthreads();

    // hoist W fragments into registers (loop-invariant across all 512 steps)
    const uint32_t aoff = ((lane & 15) * RLDS + (lane >> 4) * 8) * 2;
    const uint32_t bbase = (uint32_t)(wn * 16 * RLDS * 2);
    uint32_t bf[16][4];
#pragma unroll
    for (int ki = 0; ki < 16; ki++)
        ldm4(bf[ki], smb + OW_S + bbase + aoff + ki * 32);   // 16 elems * 2B

    // per-thread pointwise mapping: batch m = tid&15, 2 units
    const int m_loc = tid & 15;
    const int ug = tid >> 4;              // 0..15
    const int b_glob = mg * 16 + m_loc;
    const int u0g = ns * 32 + ug * 2;     // global unit index (col in A)
    const int len = lengths[b_glob];

    float cs[2] = {0.f, 0.f};
    float hs[2] = {0.f, 0.f};

    const float* xpbase = g_xproj + (size_t)dir * TT * BB * G4;

    float4 pg[2];
    {
        int t0 = dir ? (TT - 1) : 0;
        const float4* src = (const float4*)(xpbase + ((size_t)t0 * BB + b_glob) * G4 + u0g * 4);
        pg[0] = src[0]; pg[1] = src[1];
    }

    const uint32_t laddr_off = (m_loc * RLDS + u0g) * 2;

    CLU_ARRIVE(); CLU_WAIT();   // zeroed A visible cluster-wide

    for (int s = 0; s < TT; s++) {
        int t = dir ? (TT - 1 - s) : s;
        const uint32_t pA = smb + ((s & 1) ? OA_H1 : OA_H0);

        // mma: S[16 x 128] = h @ Whh_slice^T (fp16, W frags in regs)
        float acc[2][4];
#pragma unroll
        for (int ni = 0; ni < 2; ni++)
#pragma unroll
            for (int q = 0; q < 4; q++) acc[ni][q] = 0.f;

#pragma unroll
        for (int ki = 0; ki < 16; ki++) {
            uint32_t ah[4];
            ldm4(ah, pA + aoff + ki * 32);
            mma_f16(acc[0], ah, bf[ki][0], bf[ki][2]);
            mma_f16(acc[1], ah, bf[ki][1], bf[ki][3]);
        }

        // accumulators -> smem S
#pragma unroll
        for (int ni = 0; ni < 2; ni++) {
            int col = wn * 16 + ni * 8 + tig * 2;
            *(float2*)&S[gid * 132 + col] = make_float2(acc[ni][0], acc[ni][1]);
            *(float2*)&S[(gid + 8) * 132 + col] = make_float2(acc[ni][2], acc[ni][3]);
        }
        __syncthreads();

        // pointwise: (m_loc, units u0g, u0g+1)
        const bool val = (t < len);
        __half oh[2];
        float of2[2];
#pragma unroll
        for (int j = 0; j < 2; j++) {
            float4 sg = *(const float4*)&S[m_loc * 132 + (ug * 2 + j) * 4];
            float4 g = pg[j];
            float gi = sigmfast(sg.x + g.x);
            float gf = sigmfast(sg.y + g.y);
            float gg = tanhfast(sg.z + g.z);
            float go = sigmfast(sg.w + g.w);
            float cn = gf * cs[j] + gi * gg;
            float hn = go * tanhfast(cn);
            if (val) { cs[j] = cn; hs[j] = hn; }
            float ov = val ? hn : 0.f;
            oh[j] = __float2half_rn(ov);
            of2[j] = ov;
        }
        // push h (2 units = 1 u32) into all 8 cluster CTAs' A[p^1]
        {
            uint32_t vh = (uint32_t)__half_as_ushort(__float2half_rn(hs[0])) |
                          ((uint32_t)__half_as_ushort(__float2half_rn(hs[1])) << 16);
            uint32_t la = smb + ((s & 1) ? OA_H0 : OA_H1) + laddr_off;
#pragma unroll
            for (uint32_t r = 0; r < 8; r++)
                st_clu(mapa_u32(la, r), vh);
        }

        CLU_ARRIVE();   // pushes ordered/released; overlap global work with skew

        if (layer == 0) {
            size_t off = ((size_t)t * BB + b_glob) * DIN + dir * HH + u0g;
            *(uint32_t*)(g_i2h + off) = (uint32_t)__half_as_ushort(oh[0]) |
                                        ((uint32_t)__half_as_ushort(oh[1]) << 16);
        } else {
            *(float2*)(dout + ((size_t)b_glob * TT + t) * 512 + dir * HH + u0g) =
                make_float2(of2[0], of2[1]);
        }
        if (s + 1 < TT) {
            int t2 = dir ? (TT - 2 - s) : (s + 1);
            const float4* src = (const float4*)(xpbase + ((size_t)t2 * BB + b_glob) * G4 + u0g * 4);
            pg[0] = src[0]; pg[1] = src[1];
        }

        CLU_WAIT();     // peers' pushes visible; also full block barrier
    }

    // final h_n / c_n
    {
        size_t o = (size_t)((layer * 2 + dir) * BB + b_glob) * HH + u0g;
        *(float2*)(dout + HN_OFF + o) = make_float2(hs[0], hs[1]);
        *(float2*)(dout + CN_OFF + o) = make_float2(cs[0], cs[1]);
    }
}

// ---------------- launch -----------------------------------------------------
extern "C" void kernel_launch(void* const* d_in, const int* in_sizes, int n_in,
                              void* d_out, int out_size)
{
    const float* x   = (const float*)d_in[0];
    const int*   len = (const int*)d_in[1];
    const float* Wih = (const float*)d_in[2];
    const float* Whh = (const float*)d_in[3];
    const float* bih = (const float*)d_in[4];
    const float* bhh = (const float*)d_in[5];
    float* out = (float*)d_out;

    cudaFuncSetAttribute(k_lstm, cudaFuncAttributeMaxDynamicSharedMemorySize, SM_REC);
    cudaFuncSetAttribute(k_gemm_tc, cudaFuncAttributeMaxDynamicSharedMemorySize, SM_GEMM);

    k_split_x<<<(MM * (DIN / 4) + 255) / 256, 256>>>(x);
    k_split_w<<<(4 * G4 * (DIN / 4) + 255) / 256, 256>>>(Wih, bih, bhh);

    k_gemm_tc<<<dim3(G4 / 128, MM / 128, 2), 256, SM_GEMM>>>(0);
    k_lstm<<<128, 256, SM_REC>>>(Whh, len, out, 0);
    k_gemm_tc<<<dim3(G4 / 128, MM / 128, 2), 256, SM_GEMM>>>(1);
    k_lstm<<<128, 256, SM_REC>>>(Whh, len, out, 1);
}

// round 10
// speedup vs baseline: 5.8320x; 1.1027x over previous
#include <cuda_runtime.h>
#include <cuda_fp16.h>
#include <cstdint>

#define BB   128      // batch
#define TT   512      // time
#define DIN  512      // input dim (also 2H for layer 1)
#define HH   256      // hidden
#define G4   1024     // 4*H
#define MM   (TT*BB)  // 65536 rows of A

#define HN_OFF 33554432ULL              // B*T*512
#define CN_OFF (HN_OFF + 131072ULL)     // + 4*B*H

// ---------------- device scratch (static, no runtime alloc) ----------------
__device__ __align__(256) __half g_xh[(size_t)MM * DIN];   // x fp16 (T,B,D)
__device__ __align__(256) __half g_i2h[(size_t)MM * DIN];  // layer-1 input fp16
__device__ __align__(256) __half g_w[4ULL * G4 * DIN];     // permuted W_ih (fp16)
__device__ __align__(256) float g_bias[4 * G4];            // permuted b_ih+b_hh
__device__ __align__(256) float g_xproj[2ULL * TT * BB * G4];  // gate preacts

// ---------------- small helpers --------------------------------------------
__device__ __forceinline__ float tanhfast(float x) {
    float y; asm("tanh.approx.f32 %0, %1;" : "=f"(y) : "f"(x)); return y;
}
__device__ __forceinline__ float sigmfast(float x) {
    return fmaf(0.5f, tanhfast(0.5f * x), 0.5f);
}
__device__ __forceinline__ uint32_t smem_u32(const void* p) {
    uint32_t a;
    asm("{ .reg .u64 t; cvta.to.shared.u64 t, %1; cvt.u32.u64 %0, t; }" : "=r"(a) : "l"(p));
    return a;
}

// ---------------- mma.sync / ldmatrix / cp.async / cluster wrappers ---------
__device__ __forceinline__ void ldm4(uint32_t* r, uint32_t addr) {
    asm volatile("ldmatrix.sync.aligned.m8n8.x4.shared.b16 {%0,%1,%2,%3}, [%4];"
                 : "=r"(r[0]), "=r"(r[1]), "=r"(r[2]), "=r"(r[3]) : "r"(addr));
}
__device__ __forceinline__ void mma_f16(float* d, const uint32_t* a,
                                        uint32_t b0, uint32_t b1) {
    asm volatile(
        "mma.sync.aligned.m16n8k16.row.col.f32.f16.f16.f32 "
        "{%0,%1,%2,%3}, {%4,%5,%6,%7}, {%8,%9}, {%0,%1,%2,%3};"
        : "+f"(d[0]), "+f"(d[1]), "+f"(d[2]), "+f"(d[3])
        : "r"(a[0]), "r"(a[1]), "r"(a[2]), "r"(a[3]), "r"(b0), "r"(b1));
}
__device__ __forceinline__ void cpasync16(uint32_t dst, const void* src) {
    asm volatile("cp.async.cg.shared.global [%0], [%1], 16;" :: "r"(dst), "l"(src));
}
#define CP_COMMIT() asm volatile("cp.async.commit_group;" ::: "memory")
#define CP_WAIT(n)  asm volatile("cp.async.wait_group %0;" :: "n"(n) : "memory")
#define CLU_ARRIVE() asm volatile("barrier.cluster.arrive.aligned;" ::: "memory")
#define CLU_WAIT()   asm volatile("barrier.cluster.wait.aligned;" ::: "memory")
__device__ __forceinline__ uint32_t mapa_u32(uint32_t laddr, uint32_t rank) {
    uint32_t r;
    asm volatile("mapa.shared::cluster.u32 %0, %1, %2;" : "=r"(r) : "r"(laddr), "r"(rank));
    return r;
}
__device__ __forceinline__ void st_clu(uint32_t addr, uint32_t v) {
    asm volatile("st.shared::cluster.u32 [%0], %1;" :: "r"(addr), "r"(v));
}

// ---------------- transpose x: (B,T,D) fp32 -> (T,B,D) fp16 ------------------
__global__ void k_split_x(const float* __restrict__ x)
{
    int i = blockIdx.x * blockDim.x + threadIdx.x;       // float4 index
    const int N4 = MM * (DIN / 4);
    if (i >= N4) return;
    int k4 = i & 127;
    int bt = i >> 7;
    int t = bt & (TT - 1);
    int b = bt >> 9;
    float4 v = ((const float4*)x)[i];
    __half h[4];
    h[0] = __float2half_rn(v.x); h[1] = __float2half_rn(v.y);
    h[2] = __float2half_rn(v.z); h[3] = __float2half_rn(v.w);
    size_t off = ((size_t)t * BB + b) * DIN + k4 * 4;
    *(uint2*)(g_xh + off) = *(uint2*)h;
}

// ---------------- convert + permute weights (fp16 single) -------------------
__global__ void k_split_w(const float* __restrict__ Wih, const float* __restrict__ bih,
                          const float* __restrict__ bhh)
{
    int i = blockIdx.x * blockDim.x + threadIdx.x;       // (ld, n, k4)
    if (i >= 4 * G4 * (DIN / 4)) return;
    int k4 = i & 127;
    int rest = i >> 7;
    int n = rest & (G4 - 1);
    int ld = rest >> 10;
    int r = (n & 3) * HH + (n >> 2);
    float4 v = *(const float4*)(Wih + ((size_t)ld * G4 + r) * DIN + k4 * 4);
    __half h[4];
    h[0] = __float2half_rn(v.x); h[1] = __float2half_rn(v.y);
    h[2] = __float2half_rn(v.z); h[3] = __float2half_rn(v.w);
    size_t off = ((size_t)ld * G4 + n) * DIN + k4 * 4;
    *(uint2*)(g_w + off) = *(uint2*)h;
    if (k4 == 0)
        g_bias[ld * G4 + n] = bih[ld * G4 + r] + bhh[ld * G4 + r];
}

// ---------------- mma.sync input-projection GEMM (1-term fp16, 3-stage) ------
#define KC     32
#define NCH    (DIN / KC)                  // 16 chunks
#define LDS_T  40
#define ARR_B  (128 * LDS_T * 2)           // 10240
#define STG_B  (2 * ARR_B)                 // 20480  (A + W)
#define SMO_BIAS  0
#define SMO_TILES 512
#define SM_GEMM   (SMO_TILES + 3 * STG_B)  // 61952

__global__ void __launch_bounds__(256, 2) k_gemm_tc(int layer)
{
    extern __shared__ char smx[];
    const uint32_t smb = smem_u32(smx);
    const int tid = threadIdx.x;
    const int lane = tid & 31;
    const int w   = tid >> 5;
    const int wm  = w & 1;
    const int wn  = w >> 1;
    const int dir = blockIdx.z;
    const int mb  = blockIdx.y * 128;
    const int nb  = blockIdx.x * 128;

    const __half* Ah = layer ? g_i2h : g_xh;
    const __half* Wd = g_w + (size_t)(layer * 2 + dir) * G4 * DIN;

    float* bs = (float*)(smx + SMO_BIAS);
    if (tid < 128) bs[tid] = g_bias[(layer * 2 + dir) * G4 + nb + tid];

    auto issue_stage = [&](int ch) {
        const int kc = ch * KC;
        const uint32_t sb = smb + SMO_TILES + (ch % 3) * STG_B;
#pragma unroll
        for (int j = 0; j < 4; j++) {
            int c = tid + j * 256;
            int arr = c >> 9, rem = c & 511, row = rem >> 2, ck = rem & 3;
            uint32_t dst = sb + arr * ARR_B + row * (LDS_T * 2) + ck * 16;
            const __half* src = (arr == 0)
                ? Ah + (size_t)(mb + row) * DIN + kc + ck * 8
                : Wd + (size_t)(nb + row) * DIN + kc + ck * 8;
            cpasync16(dst, src);
        }
        CP_COMMIT();
    };

    issue_stage(0);
    issue_stage(1);

    float acc[4][4][4];
#pragma unroll
    for (int mi = 0; mi < 4; mi++)
#pragma unroll
        for (int ni = 0; ni < 4; ni++)
#pragma unroll
            for (int q = 0; q < 4; q++) acc[mi][ni][q] = 0.f;

    for (int ch = 0; ch < NCH; ch++) {
        if (ch + 2 < NCH) { issue_stage(ch + 2); CP_WAIT(2); }
        else if (ch + 1 < NCH) { CP_WAIT(1); }
        else { CP_WAIT(0); }
        __syncthreads();

        const uint32_t sA = smb + SMO_TILES + (ch % 3) * STG_B;
        const uint32_t sB = sA + ARR_B;

#pragma unroll
        for (int ks = 0; ks < 2; ks++) {
            const int k0 = ks * 16;
            const uint32_t aoff = ((lane & 15) * LDS_T + k0 + (lane >> 4) * 8) * 2;
            uint32_t ah[4][4];
#pragma unroll
            for (int mi = 0; mi < 4; mi++) {
                uint32_t ro = (wm * 64 + mi * 16) * (LDS_T * 2);
                ldm4(ah[mi], sA + ro + aoff);
            }
            uint32_t bh[2][4];
#pragma unroll
            for (int nj = 0; nj < 2; nj++) {
                uint32_t ro = (wn * 32 + nj * 16) * (LDS_T * 2);
                ldm4(bh[nj], sB + ro + aoff);
            }
#pragma unroll
            for (int mi = 0; mi < 4; mi++)
#pragma unroll
                for (int ni = 0; ni < 4; ni++) {
                    int nj = ni >> 1, hf = ni & 1;
                    mma_f16(acc[mi][ni], ah[mi], bh[nj][hf], bh[nj][hf + 2]);
                }
        }
        __syncthreads();
    }

    float* xp = g_xproj + (size_t)dir * TT * BB * G4;
    const int gid = lane >> 2, tig = lane & 3;
#pragma unroll
    for (int mi = 0; mi < 4; mi++) {
#pragma unroll
        for (int ni = 0; ni < 4; ni++) {
            int col = wn * 32 + ni * 8 + tig * 2;
            float b0 = bs[col], b1 = bs[col + 1];
            int r0 = mb + wm * 64 + mi * 16 + gid;
            float2 v0 = make_float2(acc[mi][ni][0] + b0, acc[mi][ni][1] + b1);
            float2 v1 = make_float2(acc[mi][ni][2] + b0, acc[mi][ni][3] + b1);
            *(float2*)(xp + (size_t)r0 * G4 + nb + col) = v0;
            *(float2*)(xp + (size_t)(r0 + 8) * G4 + nb + col) = v1;
        }
    }
}

// ---------------- recurrent persistent kernel (cluster + DSMEM, 16 warps) ----
// grid = 2 dir x 8 bgroup (M=16) x 8 nslice (N=128).  Cluster = the 8 nslices.
// 16 warps: warp pair (w, w+8) shares 16 gate cols, splits K (0-127 / 128-255).
#define RLDS  264                          // padded row stride (fp16 elems)
#define OW_S  0                            // W slice: 128 x 256 fp16 = 67584
#define AB_SZ (16 * RLDS * 2)              // 8448 per A buffer
#define OA_H0 (OW_S + 128 * RLDS * 2)      // 67584
#define OA_H1 (OA_H0 + AB_SZ)              // 76032
#define OS_S  (OA_H1 + AB_SZ)              // 84480  S:  16 x 132 f32
#define OS_S2 (OS_S + 16 * 132 * 4)        // 92928  S2: 16 x 132 f32
#define SM_REC (OS_S2 + 16 * 132 * 4)      // 101376

__global__ void __launch_bounds__(512) __cluster_dims__(8, 1, 1)
k_lstm(const float* __restrict__ Whh, const int* __restrict__ lengths,
       float* __restrict__ dout, int layer)
{
    extern __shared__ char smx[];
    const uint32_t smb = smem_u32(smx);
    float* S  = (float*)(smx + OS_S);
    float* S2 = (float*)(smx + OS_S2);

    const int cid = blockIdx.x >> 3;      // cluster id 0..15
    const int dir = cid >> 3;             // 0..1
    const int mg  = cid & 7;              // batch group 0..7 (M=16)
    const int ns  = blockIdx.x & 7;       // n-slice (== cluster ctarank)
    const int tid = threadIdx.x;
    const int lane = tid & 31;
    const int wid  = tid >> 5;            // 0..15
    const int wn2  = wid & 7;             // 16-col slice
    const int kh   = wid >> 3;            // K half 0/1
    const int gid = lane >> 2, tig = lane & 3;

    const float* W = Whh + (size_t)(layer * 2 + dir) * G4 * HH;

    // resident W_hh slice (128 gate cols x 256) -> smem fp16, once
    for (int idx = tid; idx < 128 * 256; idx += 512) {
        int nl = idx >> 8; int k = idx & 255;
        int n = ns * 128 + nl;
        int row = (n & 3) * HH + (n >> 2);
        *(__half*)(smx + OW_S + (nl * RLDS + k) * 2) = __float2half_rn(W[(size_t)row * HH + k]);
    }
    // zero both parities of A
    for (int idx = tid; idx < 2 * AB_SZ / 4; idx += 512)
        *(uint32_t*)(smx + OA_H0 + idx * 4) = 0;
    __syncthreads();

    // hoist W fragments: this warp's 16 cols x its K-half (8 k-iters)
    const uint32_t aoff = ((lane & 15) * RLDS + (lane >> 4) * 8 + kh * 128) * 2;
    const uint32_t bbase = (uint32_t)(wn2 * 16 * RLDS * 2);
    uint32_t bf[8][4];
#pragma unroll
    for (int ki = 0; ki < 8; ki++)
        ldm4(bf[ki], smb + OW_S + bbase + aoff + ki * 32);

    // pointwise mapping: unit u = lane (0..31), batch m = wid (0..15)
    const int u = lane;
    const int m = wid;
    const int b_glob = mg * 16 + m;
    const int u0g = ns * 32 + u;          // global unit col in A
    const int len = lengths[b_glob];

    float cs = 0.f, hs = 0.f;

    const float* xpbase = g_xproj + (size_t)dir * TT * BB * G4;

    float4 pg;
    {
        int t0 = dir ? (TT - 1) : 0;
        pg = *(const float4*)(xpbase + ((size_t)t0 * BB + b_glob) * G4 + u0g * 4);
    }

    const uint32_t laddr_off = (m * RLDS + u0g) * 2;   // even-lane threads push

    CLU_ARRIVE(); CLU_WAIT();   // zeroed A visible cluster-wide

    for (int s = 0; s < TT; s++) {
        int t = dir ? (TT - 1 - s) : s;
        const uint32_t pA = smb + ((s & 1) ? OA_H1 : OA_H0);

        // mma: partial S[16 x 128] over this warp's K half
        float acc[2][4];
#pragma unroll
        for (int ni = 0; ni < 2; ni++)
#pragma unroll
            for (int q = 0; q < 4; q++) acc[ni][q] = 0.f;

#pragma unroll
        for (int ki = 0; ki < 8; ki++) {
            uint32_t ah[4];
            ldm4(ah, pA + aoff + ki * 32);
            mma_f16(acc[0], ah, bf[ki][0], bf[ki][2]);
            mma_f16(acc[1], ah, bf[ki][1], bf[ki][3]);
        }

        // partial accumulators -> S (k-half 0) / S2 (k-half 1)
        float* Sk = kh ? S2 : S;
#pragma unroll
        for (int ni = 0; ni < 2; ni++) {
            int col = wn2 * 16 + ni * 8 + tig * 2;
            *(float2*)&Sk[gid * 132 + col] = make_float2(acc[ni][0], acc[ni][1]);
            *(float2*)&Sk[(gid + 8) * 132 + col] = make_float2(acc[ni][2], acc[ni][3]);
        }
        __syncthreads();

        // pointwise: 1 (batch m, unit u) per thread
        const bool val = (t < len);
        float4 s1 = *(const float4*)&S[m * 132 + u * 4];
        float4 s2 = *(const float4*)&S2[m * 132 + u * 4];
        float gi = sigmfast(s1.x + s2.x + pg.x);
        float gf = sigmfast(s1.y + s2.y + pg.y);
        float gg = tanhfast(s1.z + s2.z + pg.z);
        float go = sigmfast(s1.w + s2.w + pg.w);
        float cn = gf * cs + gi * gg;
        float hn = go * tanhfast(cn);
        if (val) { cs = cn; hs = hn; }
        float ov = val ? hn : 0.f;

        // pack pairs via shuffle (even lane owns units u, u+1)
        float hs2 = __shfl_down_sync(0xffffffffu, hs, 1);
        float ov2 = __shfl_down_sync(0xffffffffu, ov, 1);
        uint32_t vh = (uint32_t)__half_as_ushort(__float2half_rn(hs)) |
                      ((uint32_t)__half_as_ushort(__float2half_rn(hs2)) << 16);
        uint32_t vo = (uint32_t)__half_as_ushort(__float2half_rn(ov)) |
                      ((uint32_t)__half_as_ushort(__float2half_rn(ov2)) << 16);

        // push h (2 units = 1 u32) into all 8 cluster CTAs' A[p^1]
        if (!(lane & 1)) {
            uint32_t la = smb + ((s & 1) ? OA_H0 : OA_H1) + laddr_off;
#pragma unroll
            for (uint32_t r = 0; r < 8; r++)
                st_clu(mapa_u32(la, r), vh);
        }

        CLU_ARRIVE();   // pushes ordered/released; overlap global work with skew

        if (layer == 0) {
            if (!(lane & 1)) {
                size_t off = ((size_t)t * BB + b_glob) * DIN + dir * HH + u0g;
                *(uint32_t*)(g_i2h + off) = vo;
            }
        } else {
            dout[((size_t)b_glob * TT + t) * 512 + dir * HH + u0g] = ov;
        }
        if (s + 1 < TT) {
            int t2 = dir ? (TT - 2 - s) : (s + 1);
            pg = *(const float4*)(xpbase + ((size_t)t2 * BB + b_glob) * G4 + u0g * 4);
        }

        CLU_WAIT();     // peers' pushes visible; also full block barrier
    }

    // final h_n / c_n (coalesced: lane-major units)
    {
        size_t o = (size_t)((layer * 2 + dir) * BB + b_glob) * HH + u0g;
        dout[HN_OFF + o] = hs;
        dout[CN_OFF + o] = cs;
    }
}

// ---------------- launch -----------------------------------------------------
extern "C" void kernel_launch(void* const* d_in, const int* in_sizes, int n_in,
                              void* d_out, int out_size)
{
    const float* x   = (const float*)d_in[0];
    const int*   len = (const int*)d_in[1];
    const float* Wih = (const float*)d_in[2];
    const float* Whh = (const float*)d_in[3];
    const float* bih = (const float*)d_in[4];
    const float* bhh = (const float*)d_in[5];
    float* out = (float*)d_out;

    cudaFuncSetAttribute(k_lstm, cudaFuncAttributeMaxDynamicSharedMemorySize, SM_REC);
    cudaFuncSetAttribute(k_gemm_tc, cudaFuncAttributeMaxDynamicSharedMemorySize, SM_GEMM);

    k_split_x<<<(MM * (DIN / 4) + 255) / 256, 256>>>(x);
    k_split_w<<<(4 * G4 * (DIN / 4) + 255) / 256, 256>>>(Wih, bih, bhh);

    k_gemm_tc<<<dim3(G4 / 128, MM / 128, 2), 256, SM_GEMM>>>(0);
    k_lstm<<<128, 512, SM_REC>>>(Whh, len, out, 0);
    k_gemm_tc<<<dim3(G4 / 128, MM / 128, 2), 256, SM_GEMM>>>(1);
    k_lstm<<<128, 512, SM_REC>>>(Whh, len, out, 1);
}